// round 1
// baseline (speedup 1.0000x reference)
#include <cuda_runtime.h>
#include <math_constants.h>

// Problem constants
#define BB 128
#define TT 256
#define CC 384
#define HH 6
#define HS 64
#define MM (BB*TT)   // 32768 rows

// Scratch (device globals; no allocations allowed)
__device__ float g_q[(size_t)BB*HH*TT*HS];   // [B,H,T,HS]
__device__ float g_k[(size_t)BB*HH*TT*HS];
__device__ float g_v[(size_t)BB*HH*TT*HS];
__device__ float g_o[(size_t)BB*TT*CC];      // attention output [B,T,C]

// ---------------------------------------------------------------------------
// Kernel 1: QKV projection.
// grid = (MM/128, 18): blockIdx.y -> (matrix in {q,k,v}, head)
// Computes O[b,h,t,d] = sum_c x[b,t,c] * W[h,c,d] for the chosen matrix.
// Tile: 128 rows x 64 cols (full head), K-step 16. 256 threads, 8x4 microtile.
// ---------------------------------------------------------------------------
__global__ __launch_bounds__(256) void qkv_kernel(
    const float* __restrict__ x,
    const float* __restrict__ Wq,
    const float* __restrict__ Wk,
    const float* __restrict__ Wv)
{
    __shared__ float sA[16][132];  // [kk][row], padded
    __shared__ float sB[16][64];   // [kk][col]

    const int m0  = blockIdx.x * 128;
    const int mat = blockIdx.y / HH;
    const int h   = blockIdx.y % HH;
    const float* W = (mat == 0 ? Wq : (mat == 1 ? Wk : Wv)) + (size_t)h * CC * HS;
    float* O = (mat == 0 ? g_q : (mat == 1 ? g_k : g_v));

    const int tid = threadIdx.x;
    const int tx = tid & 15;   // 0..15 -> 4 cols each
    const int ty = tid >> 4;   // 0..15 -> 8 rows each

    float acc[8][4];
    #pragma unroll
    for (int i = 0; i < 8; i++)
        #pragma unroll
        for (int j = 0; j < 4; j++) acc[i][j] = 0.f;

    for (int k0 = 0; k0 < CC; k0 += 16) {
        // Load A tile (128x16) transposed into sA[kk][row]
        #pragma unroll
        for (int i = 0; i < 2; i++) {
            int f = tid + i * 256;        // 0..511 float4s
            int row = f >> 2;             // 0..127
            int c4 = f & 3;               // 0..3
            float4 v = *(const float4*)(x + (size_t)(m0 + row) * CC + k0 + c4 * 4);
            sA[c4*4 + 0][row] = v.x;
            sA[c4*4 + 1][row] = v.y;
            sA[c4*4 + 2][row] = v.z;
            sA[c4*4 + 3][row] = v.w;
        }
        // Load B tile (16x64)
        {
            int kk = tid >> 4, c4 = tid & 15;
            *(float4*)&sB[kk][c4 * 4] =
                *(const float4*)(W + (size_t)(k0 + kk) * HS + c4 * 4);
        }
        __syncthreads();

        #pragma unroll
        for (int kk = 0; kk < 16; kk++) {
            float4 a0 = *(const float4*)&sA[kk][ty * 8];
            float4 a1 = *(const float4*)&sA[kk][ty * 8 + 4];
            float4 bv = *(const float4*)&sB[kk][tx * 4];
            float a[8] = {a0.x, a0.y, a0.z, a0.w, a1.x, a1.y, a1.z, a1.w};
            float b[4] = {bv.x, bv.y, bv.z, bv.w};
            #pragma unroll
            for (int i = 0; i < 8; i++)
                #pragma unroll
                for (int j = 0; j < 4; j++)
                    acc[i][j] += a[i] * b[j];
        }
        __syncthreads();
    }

    // Write to [B,H,T,HS] layout
    #pragma unroll
    for (int i = 0; i < 8; i++) {
        int m = m0 + ty * 8 + i;
        int b = m >> 8;            // T = 256
        int t = m & (TT - 1);
        float4 r = make_float4(acc[i][0], acc[i][1], acc[i][2], acc[i][3]);
        *(float4*)(O + ((size_t)((b * HH + h) * TT + t)) * HS + tx * 4) = r;
    }
}

// ---------------------------------------------------------------------------
// Kernel 2: causal attention per (b,h). One block = one (b,h).
// K,V for the whole sequence live in smem (128 KB). One thread per query row,
// register-resident q/accumulator, online softmax. All lanes read the same
// K/V row per step -> smem broadcast; kernel is FFMA-bound.
// Writes directly into [B,T,H*hs] layout for the projection.
// ---------------------------------------------------------------------------
__global__ __launch_bounds__(256) void attn_kernel()
{
    extern __shared__ float smem[];
    float* ks = smem;              // [256][64]
    float* vs = smem + TT * HS;    // [256][64]

    const int bh = blockIdx.x;
    const int b = bh / HH, h = bh % HH;
    const int t = threadIdx.x;
    const size_t base = (size_t)bh * TT * HS;

    // Cooperative load of K,V into smem (float4, fully coalesced)
    {
        const float4* gk4 = (const float4*)(g_k + base);
        const float4* gv4 = (const float4*)(g_v + base);
        float4* ks4 = (float4*)ks;
        float4* vs4 = (float4*)vs;
        #pragma unroll
        for (int i = 0; i < 16; i++) {
            ks4[t + i * 256] = gk4[t + i * 256];
            vs4[t + i * 256] = gv4[t + i * 256];
        }
    }

    // Load this thread's q row into registers
    float4 q4[16];
    {
        const float4* gq4 = (const float4*)(g_q + base + (size_t)t * HS);
        #pragma unroll
        for (int i = 0; i < 16; i++) q4[i] = gq4[i];
    }
    __syncthreads();

    float mmax = -CUDART_INF_F;
    float l = 0.f;
    float4 acc[16];
    #pragma unroll
    for (int i = 0; i < 16; i++) acc[i] = make_float4(0.f, 0.f, 0.f, 0.f);

    for (int s = 0; s <= t; s++) {
        const float4* kr = (const float4*)(ks + s * HS);
        float4 sv = make_float4(0.f, 0.f, 0.f, 0.f);
        #pragma unroll
        for (int i = 0; i < 16; i++) {
            float4 kv = kr[i];
            sv.x += q4[i].x * kv.x;
            sv.y += q4[i].y * kv.y;
            sv.z += q4[i].z * kv.z;
            sv.w += q4[i].w * kv.w;
        }
        float sc = ((sv.x + sv.y) + (sv.z + sv.w)) * 0.125f;  // 1/sqrt(64)

        if (sc > mmax) {
            float corr = __expf(mmax - sc);   // exp(-inf)=0 handles first iter
            mmax = sc;
            l *= corr;
            #pragma unroll
            for (int i = 0; i < 16; i++) {
                acc[i].x *= corr; acc[i].y *= corr;
                acc[i].z *= corr; acc[i].w *= corr;
            }
        }
        float p = __expf(sc - mmax);
        l += p;

        const float4* vr = (const float4*)(vs + s * HS);
        #pragma unroll
        for (int i = 0; i < 16; i++) {
            float4 vv = vr[i];
            acc[i].x += p * vv.x; acc[i].y += p * vv.y;
            acc[i].z += p * vv.z; acc[i].w += p * vv.w;
        }
    }

    float inv = 1.f / l;
    float* op = g_o + ((size_t)(b * TT + t)) * CC + h * HS;
    #pragma unroll
    for (int i = 0; i < 16; i++) {
        float4 r = make_float4(acc[i].x * inv, acc[i].y * inv,
                               acc[i].z * inv, acc[i].w * inv);
        *(float4*)(op + i * 4) = r;
    }
}

// ---------------------------------------------------------------------------
// Kernel 3: output projection  out = g_o @ Wp + bp
// Same tiling as kernel 1. grid = (MM/128, CC/64)
// ---------------------------------------------------------------------------
__global__ __launch_bounds__(256) void proj_kernel(
    const float* __restrict__ Wp,
    const float* __restrict__ bp,
    float* __restrict__ out)
{
    __shared__ float sA[16][132];
    __shared__ float sB[16][64];

    const int m0 = blockIdx.x * 128;
    const int n0 = blockIdx.y * 64;
    const int tid = threadIdx.x;
    const int tx = tid & 15, ty = tid >> 4;

    float acc[8][4];
    #pragma unroll
    for (int i = 0; i < 8; i++)
        #pragma unroll
        for (int j = 0; j < 4; j++) acc[i][j] = 0.f;

    for (int k0 = 0; k0 < CC; k0 += 16) {
        #pragma unroll
        for (int i = 0; i < 2; i++) {
            int f = tid + i * 256;
            int row = f >> 2, c4 = f & 3;
            float4 v = *(const float4*)(g_o + (size_t)(m0 + row) * CC + k0 + c4 * 4);
            sA[c4*4 + 0][row] = v.x;
            sA[c4*4 + 1][row] = v.y;
            sA[c4*4 + 2][row] = v.z;
            sA[c4*4 + 3][row] = v.w;
        }
        {
            int kk = tid >> 4, c4 = tid & 15;
            *(float4*)&sB[kk][c4 * 4] =
                *(const float4*)(Wp + (size_t)(k0 + kk) * CC + n0 + c4 * 4);
        }
        __syncthreads();

        #pragma unroll
        for (int kk = 0; kk < 16; kk++) {
            float4 a0 = *(const float4*)&sA[kk][ty * 8];
            float4 a1 = *(const float4*)&sA[kk][ty * 8 + 4];
            float4 bv = *(const float4*)&sB[kk][tx * 4];
            float a[8] = {a0.x, a0.y, a0.z, a0.w, a1.x, a1.y, a1.z, a1.w};
            float b[4] = {bv.x, bv.y, bv.z, bv.w};
            #pragma unroll
            for (int i = 0; i < 8; i++)
                #pragma unroll
                for (int j = 0; j < 4; j++)
                    acc[i][j] += a[i] * b[j];
        }
        __syncthreads();
    }

    float4 bias = *(const float4*)(bp + n0 + tx * 4);
    #pragma unroll
    for (int i = 0; i < 8; i++) {
        int m = m0 + ty * 8 + i;
        float4 r = make_float4(acc[i][0] + bias.x, acc[i][1] + bias.y,
                               acc[i][2] + bias.z, acc[i][3] + bias.w);
        *(float4*)(out + (size_t)m * CC + n0 + tx * 4) = r;
    }
}

// ---------------------------------------------------------------------------
extern "C" void kernel_launch(void* const* d_in, const int* in_sizes, int n_in,
                              void* d_out, int out_size)
{
    const float* x  = (const float*)d_in[0];
    const float* Wq = (const float*)d_in[1];
    const float* Wk = (const float*)d_in[2];
    const float* Wv = (const float*)d_in[3];
    const float* Wp = (const float*)d_in[4];
    const float* bp = (const float*)d_in[5];
    float* out = (float*)d_out;

    const size_t attn_smem = 2u * TT * HS * sizeof(float);  // 128 KB
    cudaFuncSetAttribute(attn_kernel,
                         cudaFuncAttributeMaxDynamicSharedMemorySize,
                         (int)attn_smem);

    qkv_kernel<<<dim3(MM / 128, 3 * HH), 256>>>(x, Wq, Wk, Wv);
    attn_kernel<<<BB * HH, 256, attn_smem>>>();
    proj_kernel<<<dim3(MM / 128, CC / 64), 256>>>(Wp, bp, out);
}

// round 5
// speedup vs baseline: 1.4564x; 1.4564x over previous
#include <cuda_runtime.h>
#include <cuda_bf16.h>
#include <math_constants.h>
#include <cstdint>

// Problem constants
#define BB 128
#define TT 256
#define CC 384
#define HH 6
#define HS 64
#define MM (BB*TT)       // 32768 rows
#define NW 24576         // 64*384, one head's transposed weight
#define WP_OFF (18*NW)   // offset of Wp^T inside g_wt arrays

// ---------------------------------------------------------------------------
// Scratch (device globals; no allocations allowed)
// ---------------------------------------------------------------------------
__device__ __nv_bfloat16 g_xhi[(size_t)MM*CC];
__device__ __nv_bfloat16 g_xlo[(size_t)MM*CC];
__device__ __nv_bfloat16 g_wthi[WP_OFF + CC*CC];   // [18][64][384] + WpT[384][384]
__device__ __nv_bfloat16 g_wtlo[WP_OFF + CC*CC];
__device__ float g_q[(size_t)BB*HH*TT*HS];
__device__ float g_k[(size_t)BB*HH*TT*HS];
__device__ float g_v[(size_t)BB*HH*TT*HS];
__device__ __nv_bfloat16 g_ohi[(size_t)MM*CC];     // attention out, bf16 split
__device__ __nv_bfloat16 g_olo[(size_t)MM*CC];

// ---------------------------------------------------------------------------
// Helpers
// ---------------------------------------------------------------------------
__device__ __forceinline__ uint32_t smem_u32(const void* p) {
    uint32_t a;
    asm("{ .reg .u64 t; cvta.to.shared.u64 t, %1; cvt.u32.u64 %0, t; }"
        : "=r"(a) : "l"(p));
    return a;
}

__device__ __forceinline__ void ldm_x4(uint32_t* r, uint32_t addr) {
    asm volatile("ldmatrix.sync.aligned.m8n8.x4.shared.b16 {%0,%1,%2,%3}, [%4];"
                 : "=r"(r[0]), "=r"(r[1]), "=r"(r[2]), "=r"(r[3]) : "r"(addr));
}

__device__ __forceinline__ void mma16816(float* c, const uint32_t* a, const uint32_t* b) {
    asm volatile(
        "mma.sync.aligned.m16n8k16.row.col.f32.bf16.bf16.f32 "
        "{%0,%1,%2,%3}, {%4,%5,%6,%7}, {%8,%9}, {%0,%1,%2,%3};"
        : "+f"(c[0]), "+f"(c[1]), "+f"(c[2]), "+f"(c[3])
        : "r"(a[0]), "r"(a[1]), "r"(a[2]), "r"(a[3]), "r"(b[0]), "r"(b[1]));
}

// ---------------------------------------------------------------------------
// Kernel A: convert x -> bf16 hi/lo
// ---------------------------------------------------------------------------
__global__ __launch_bounds__(256) void cvt_x_kernel(const float* __restrict__ x)
{
    int i = blockIdx.x * 256 + threadIdx.x;      // float4 index
    float4 v = ((const float4*)x)[i];
    __nv_bfloat16 h0 = __float2bfloat16_rn(v.x);
    __nv_bfloat16 h1 = __float2bfloat16_rn(v.y);
    __nv_bfloat16 h2 = __float2bfloat16_rn(v.z);
    __nv_bfloat16 h3 = __float2bfloat16_rn(v.w);
    __nv_bfloat16 l0 = __float2bfloat16_rn(v.x - __bfloat162float(h0));
    __nv_bfloat16 l1 = __float2bfloat16_rn(v.y - __bfloat162float(h1));
    __nv_bfloat16 l2 = __float2bfloat16_rn(v.z - __bfloat162float(h2));
    __nv_bfloat16 l3 = __float2bfloat16_rn(v.w - __bfloat162float(h3));
    __nv_bfloat162 H01 = __halves2bfloat162(h0, h1), H23 = __halves2bfloat162(h2, h3);
    __nv_bfloat162 L01 = __halves2bfloat162(l0, l1), L23 = __halves2bfloat162(l2, l3);
    uint2 uh, ul;
    uh.x = *reinterpret_cast<uint32_t*>(&H01); uh.y = *reinterpret_cast<uint32_t*>(&H23);
    ul.x = *reinterpret_cast<uint32_t*>(&L01); ul.y = *reinterpret_cast<uint32_t*>(&L23);
    ((uint2*)g_xhi)[i] = uh;
    ((uint2*)g_xlo)[i] = ul;
}

// ---------------------------------------------------------------------------
// Kernel B: convert + transpose weights -> Wt[g][n][k] bf16 hi/lo, g in [0,18);
// then WpT[n][k] at WP_OFF.
// ---------------------------------------------------------------------------
__global__ __launch_bounds__(256) void cvt_w_kernel(
    const float* __restrict__ Wq, const float* __restrict__ Wk,
    const float* __restrict__ Wv, const float* __restrict__ Wp)
{
    int gi = blockIdx.x * 256 + threadIdx.x;
    float v; size_t dst;
    if (gi < 18 * NW) {
        int g = gi / NW, rem = gi % NW;
        int k = rem / HS, n = rem % HS;
        int mat = g / HH, h = g % HH;
        const float* W = (mat == 0 ? Wq : (mat == 1 ? Wk : Wv));
        v = W[(size_t)h * CC * HS + (size_t)k * HS + n];
        dst = (size_t)g * NW + (size_t)n * CC + k;
    } else {
        int j = gi - 18 * NW;
        int k = j / CC, n = j % CC;
        v = Wp[(size_t)k * CC + n];
        dst = WP_OFF + (size_t)n * CC + k;
    }
    __nv_bfloat16 hi = __float2bfloat16_rn(v);
    __nv_bfloat16 lo = __float2bfloat16_rn(v - __bfloat162float(hi));
    g_wthi[dst] = hi;
    g_wtlo[dst] = lo;
}

// ---------------------------------------------------------------------------
// Kernel C: HMMA GEMM, D[128 x 64] = A[128 x 384] * B^T, bf16 2-way split
// (hi*hi + hi*lo + lo*hi). mma.sync.m16n8k16 + ldmatrix.
// MODE 0: QKV  (A = x split, B = head weight, out -> g_q/g_k/g_v fp32)
// MODE 1: proj (A = attn-out split, B = WpT slice, out -> d_out + bias)
// Block 256 threads = 8 warps; warp tile 32x32 (warp grid 4m x 2n); BK=32.
// smem rows padded to 80 B so ldmatrix row addresses are bank-conflict-free.
// ---------------------------------------------------------------------------
#define PAD 40   // bf16 elements per smem row (80 bytes)

template <int MODE>
__global__ __launch_bounds__(256) void gemm_hmma_kernel(
    const float* __restrict__ bp, float* __restrict__ out)
{
    __shared__ __nv_bfloat16 sAhi[128 * PAD];
    __shared__ __nv_bfloat16 sAlo[128 * PAD];
    __shared__ __nv_bfloat16 sBhi[64 * PAD];
    __shared__ __nv_bfloat16 sBlo[64 * PAD];

    const int tid = threadIdx.x;
    const int wid = tid >> 5, lane = tid & 31;
    const int wm = wid & 3, wn = wid >> 2;       // 4 x 2 warp grid
    const int m0 = blockIdx.x * 128;

    // sources
    const __nv_bfloat16 *Ahi, *Alo, *Bhi, *Blo;
    int mat = 0, h = 0, n0 = 0;
    if (MODE == 0) {
        int g = blockIdx.y; mat = g / HH; h = g % HH;
        Ahi = g_xhi; Alo = g_xlo;
        Bhi = g_wthi + (size_t)g * NW; Blo = g_wtlo + (size_t)g * NW;
    } else {
        n0 = blockIdx.y * 64;
        Ahi = g_ohi; Alo = g_olo;
        Bhi = g_wthi + WP_OFF + (size_t)n0 * CC;
        Blo = g_wtlo + WP_OFF + (size_t)n0 * CC;
    }

    // ldmatrix per-lane addresses
    const int qq = lane >> 3, rr = lane & 7;
    const uint32_t aHiB = smem_u32(sAhi), aLoB = smem_u32(sAlo);
    const uint32_t bHiB = smem_u32(sBhi), bLoB = smem_u32(sBlo);
    // A x4: matrices (rows0-7@k0)(rows8-15@k0)(rows0-7@k8)(rows8-15@k8)
    const uint32_t aoff = (uint32_t)((wm * 32 + (qq & 1) * 8 + rr) * 80 + (qq >> 1) * 16);
    // B x4: matrices (n0-7@k0)(n0-7@k8)(n8-15@k0)(n8-15@k8)
    const uint32_t boff = (uint32_t)((wn * 32 + (qq >> 1) * 8 + rr) * 80 + (qq & 1) * 16);

    float c[2][4][4];
    #pragma unroll
    for (int i = 0; i < 2; i++)
        #pragma unroll
        for (int j = 0; j < 4; j++)
            #pragma unroll
            for (int k = 0; k < 4; k++) c[i][j][k] = 0.f;

    #pragma unroll 1
    for (int ch = 0; ch < CC / 32; ch++) {
        const int k0 = ch * 32;
        __syncthreads();   // previous iteration's reads complete

        // ---- global -> smem (16B chunks; 4 chunks per 32-col row) ----
        #pragma unroll
        for (int i = 0; i < 2; i++) {
            int cid = tid + i * 256;          // 0..511
            int row = cid >> 2, cj = cid & 3;
            const uint4* gh = (const uint4*)(Ahi + (size_t)(m0 + row) * CC + k0 + cj * 8);
            const uint4* gl = (const uint4*)(Alo + (size_t)(m0 + row) * CC + k0 + cj * 8);
            *(uint4*)(sAhi + row * PAD + cj * 8) = *gh;
            *(uint4*)(sAlo + row * PAD + cj * 8) = *gl;
        }
        {
            int row = tid >> 2, cj = tid & 3;  // 64 rows x 4 chunks
            *(uint4*)(sBhi + row * PAD + cj * 8) =
                *(const uint4*)(Bhi + (size_t)row * CC + k0 + cj * 8);
            *(uint4*)(sBlo + row * PAD + cj * 8) =
                *(const uint4*)(Blo + (size_t)row * CC + k0 + cj * 8);
        }
        __syncthreads();

        // ---- compute: 2 k16 steps x 3 split passes ----
        #pragma unroll
        for (int ks = 0; ks < 2; ks++) {
            const uint32_t kb = ks * 32;
            uint32_t ah[2][4], al[2][4], bh[2][4], bl[2][4];
            #pragma unroll
            for (int mi = 0; mi < 2; mi++) {
                ldm_x4(ah[mi], aHiB + aoff + mi * (16 * 80) + kb);
                ldm_x4(al[mi], aLoB + aoff + mi * (16 * 80) + kb);
            }
            #pragma unroll
            for (int nt = 0; nt < 2; nt++) {
                ldm_x4(bh[nt], bHiB + boff + nt * (16 * 80) + kb);
                ldm_x4(bl[nt], bLoB + boff + nt * (16 * 80) + kb);
            }
            #pragma unroll
            for (int mi = 0; mi < 2; mi++)
                #pragma unroll
                for (int ni = 0; ni < 4; ni++)
                    mma16816(c[mi][ni], ah[mi], &bh[ni >> 1][(ni & 1) * 2]);
            #pragma unroll
            for (int mi = 0; mi < 2; mi++)
                #pragma unroll
                for (int ni = 0; ni < 4; ni++)
                    mma16816(c[mi][ni], ah[mi], &bl[ni >> 1][(ni & 1) * 2]);
            #pragma unroll
            for (int mi = 0; mi < 2; mi++)
                #pragma unroll
                for (int ni = 0; ni < 4; ni++)
                    mma16816(c[mi][ni], al[mi], &bh[ni >> 1][(ni & 1) * 2]);
        }
    }

    // ---- epilogue ----
    const int gr = lane >> 2, gc = (lane & 3) * 2;
    if (MODE == 0) {
        float* Obase = (mat == 0 ? g_q : (mat == 1 ? g_k : g_v));
        #pragma unroll
        for (int mi = 0; mi < 2; mi++) {
            #pragma unroll
            for (int hc = 0; hc < 2; hc++) {
                int m = m0 + wm * 32 + mi * 16 + hc * 8 + gr;
                int b = m >> 8, t = m & (TT - 1);
                float* O = Obase + ((size_t)((b * HH + h) * TT + t)) * HS;
                #pragma unroll
                for (int ni = 0; ni < 4; ni++) {
                    int col = wn * 32 + ni * 8 + gc;
                    float2 v = make_float2(c[mi][ni][hc * 2], c[mi][ni][hc * 2 + 1]);
                    *(float2*)(O + col) = v;
                }
            }
        }
    } else {
        #pragma unroll
        for (int mi = 0; mi < 2; mi++) {
            #pragma unroll
            for (int hc = 0; hc < 2; hc++) {
                int m = m0 + wm * 32 + mi * 16 + hc * 8 + gr;
                float* O = out + (size_t)m * CC + n0;
                #pragma unroll
                for (int ni = 0; ni < 4; ni++) {
                    int col = wn * 32 + ni * 8 + gc;
                    float2 bb = *(const float2*)(bp + n0 + col);
                    float2 v = make_float2(c[mi][ni][hc * 2] + bb.x,
                                           c[mi][ni][hc * 2 + 1] + bb.y);
                    *(float2*)(O + col) = v;
                }
            }
        }
    }
}

// ---------------------------------------------------------------------------
// Kernel D: causal attention per (b,h), SIMT online softmax.
// Epilogue emits bf16 hi/lo directly for the projection GEMM.
// ---------------------------------------------------------------------------
__global__ __launch_bounds__(256) void attn_kernel()
{
    extern __shared__ float smem[];
    float* ks = smem;
    float* vs = smem + TT * HS;

    const int bh = blockIdx.x;
    const int b = bh / HH, h = bh % HH;
    const int t = threadIdx.x;
    const size_t base = (size_t)bh * TT * HS;

    {
        const float4* gk4 = (const float4*)(g_k + base);
        const float4* gv4 = (const float4*)(g_v + base);
        float4* ks4 = (float4*)ks;
        float4* vs4 = (float4*)vs;
        #pragma unroll
        for (int i = 0; i < 16; i++) {
            ks4[t + i * 256] = gk4[t + i * 256];
            vs4[t + i * 256] = gv4[t + i * 256];
        }
    }

    float4 q4[16];
    {
        const float4* gq4 = (const float4*)(g_q + base + (size_t)t * HS);
        #pragma unroll
        for (int i = 0; i < 16; i++) q4[i] = gq4[i];
    }
    __syncthreads();

    float mmax = -CUDART_INF_F;
    float l = 0.f;
    float4 acc[16];
    #pragma unroll
    for (int i = 0; i < 16; i++) acc[i] = make_float4(0.f, 0.f, 0.f, 0.f);

    for (int s = 0; s <= t; s++) {
        const float4* kr = (const float4*)(ks + s * HS);
        float4 sv = make_float4(0.f, 0.f, 0.f, 0.f);
        #pragma unroll
        for (int i = 0; i < 16; i++) {
            float4 kv = kr[i];
            sv.x += q4[i].x * kv.x;
            sv.y += q4[i].y * kv.y;
            sv.z += q4[i].z * kv.z;
            sv.w += q4[i].w * kv.w;
        }
        float sc = ((sv.x + sv.y) + (sv.z + sv.w)) * 0.125f;

        if (sc > mmax) {
            float corr = __expf(mmax - sc);
            mmax = sc;
            l *= corr;
            #pragma unroll
            for (int i = 0; i < 16; i++) {
                acc[i].x *= corr; acc[i].y *= corr;
                acc[i].z *= corr; acc[i].w *= corr;
            }
        }
        float p = __expf(sc - mmax);
        l += p;

        const float4* vr = (const float4*)(vs + s * HS);
        #pragma unroll
        for (int i = 0; i < 16; i++) {
            float4 vv = vr[i];
            acc[i].x += p * vv.x; acc[i].y += p * vv.y;
            acc[i].z += p * vv.z; acc[i].w += p * vv.w;
        }
    }

    float inv = 1.f / l;
    __nv_bfloat16* ohi = g_ohi + ((size_t)(b * TT + t)) * CC + h * HS;
    __nv_bfloat16* olo = g_olo + ((size_t)(b * TT + t)) * CC + h * HS;
    #pragma unroll
    for (int i = 0; i < 16; i++) {
        float v0 = acc[i].x * inv, v1 = acc[i].y * inv;
        float v2 = acc[i].z * inv, v3 = acc[i].w * inv;
        __nv_bfloat16 h0 = __float2bfloat16_rn(v0), h1 = __float2bfloat16_rn(v1);
        __nv_bfloat16 h2 = __float2bfloat16_rn(v2), h3 = __float2bfloat16_rn(v3);
        __nv_bfloat16 l0 = __float2bfloat16_rn(v0 - __bfloat162float(h0));
        __nv_bfloat16 l1 = __float2bfloat16_rn(v1 - __bfloat162float(h1));
        __nv_bfloat16 l2 = __float2bfloat16_rn(v2 - __bfloat162float(h2));
        __nv_bfloat16 l3 = __float2bfloat16_rn(v3 - __bfloat162float(h3));
        __nv_bfloat162 H01 = __halves2bfloat162(h0, h1), H23 = __halves2bfloat162(h2, h3);
        __nv_bfloat162 L01 = __halves2bfloat162(l0, l1), L23 = __halves2bfloat162(l2, l3);
        uint2 uh, ul;
        uh.x = *reinterpret_cast<uint32_t*>(&H01); uh.y = *reinterpret_cast<uint32_t*>(&H23);
        ul.x = *reinterpret_cast<uint32_t*>(&L01); ul.y = *reinterpret_cast<uint32_t*>(&L23);
        *(uint2*)(ohi + i * 4) = uh;
        *(uint2*)(olo + i * 4) = ul;
    }
}

// ---------------------------------------------------------------------------
extern "C" void kernel_launch(void* const* d_in, const int* in_sizes, int n_in,
                              void* d_out, int out_size)
{
    const float* x  = (const float*)d_in[0];
    const float* Wq = (const float*)d_in[1];
    const float* Wk = (const float*)d_in[2];
    const float* Wv = (const float*)d_in[3];
    const float* Wp = (const float*)d_in[4];
    const float* bp = (const float*)d_in[5];
    float* out = (float*)d_out;

    const size_t attn_smem = 2u * TT * HS * sizeof(float);  // 128 KB
    cudaFuncSetAttribute(attn_kernel,
                         cudaFuncAttributeMaxDynamicSharedMemorySize, (int)attn_smem);

    cvt_x_kernel<<<(MM * CC / 4) / 256, 256>>>(x);
    cvt_w_kernel<<<(18 * NW + CC * CC) / 256, 256>>>(Wq, Wk, Wv, Wp);
    gemm_hmma_kernel<0><<<dim3(MM / 128, 18), 256>>>(nullptr, nullptr);
    attn_kernel<<<BB * HH, 256, attn_smem>>>();
    gemm_hmma_kernel<1><<<dim3(MM / 128, CC / 64), 256>>>(bp, out);
}

// round 9
// speedup vs baseline: 2.1986x; 1.5096x over previous
#include <cuda_runtime.h>
#include <cuda_bf16.h>
#include <cstdint>

// Problem constants
#define BB 128
#define TT 256
#define CC 384
#define HH 6
#define HS 64
#define MM (BB*TT)       // 32768 rows
#define NW 24576         // 64*384, one head's transposed weight
#define WP_OFF (18*NW)   // offset of Wp^T inside g_wt arrays

// ---------------------------------------------------------------------------
// Scratch (device globals; no allocations allowed)
// ---------------------------------------------------------------------------
__device__ __nv_bfloat16 g_xhi[(size_t)MM*CC];
__device__ __nv_bfloat16 g_xlo[(size_t)MM*CC];
__device__ __nv_bfloat16 g_wthi[WP_OFF + CC*CC];
__device__ __nv_bfloat16 g_wtlo[WP_OFF + CC*CC];
__device__ __nv_bfloat16 g_qhi[(size_t)BB*HH*TT*HS];   // [bh][t][d]
__device__ __nv_bfloat16 g_qlo[(size_t)BB*HH*TT*HS];
__device__ __nv_bfloat16 g_khi[(size_t)BB*HH*TT*HS];   // [bh][t][d]
__device__ __nv_bfloat16 g_klo[(size_t)BB*HH*TT*HS];
__device__ __nv_bfloat16 g_vthi[(size_t)BB*HH*HS*TT];  // [bh][d][t]  (transposed!)
__device__ __nv_bfloat16 g_vtlo[(size_t)BB*HH*HS*TT];
__device__ __nv_bfloat16 g_ohi[(size_t)MM*CC];         // attention out [b,t,h*64+d]
__device__ __nv_bfloat16 g_olo[(size_t)MM*CC];

// ---------------------------------------------------------------------------
// Helpers
// ---------------------------------------------------------------------------
__device__ __forceinline__ uint32_t smem_u32(const void* p) {
    uint32_t a;
    asm("{ .reg .u64 t; cvta.to.shared.u64 t, %1; cvt.u32.u64 %0, t; }"
        : "=r"(a) : "l"(p));
    return a;
}

__device__ __forceinline__ void ldm_x4(uint32_t* r, uint32_t addr) {
    asm volatile("ldmatrix.sync.aligned.m8n8.x4.shared.b16 {%0,%1,%2,%3}, [%4];"
                 : "=r"(r[0]), "=r"(r[1]), "=r"(r[2]), "=r"(r[3]) : "r"(addr));
}

__device__ __forceinline__ void mma16816(float* c, const uint32_t* a, const uint32_t* b) {
    asm volatile(
        "mma.sync.aligned.m16n8k16.row.col.f32.bf16.bf16.f32 "
        "{%0,%1,%2,%3}, {%4,%5,%6,%7}, {%8,%9}, {%0,%1,%2,%3};"
        : "+f"(c[0]), "+f"(c[1]), "+f"(c[2]), "+f"(c[3])
        : "r"(a[0]), "r"(a[1]), "r"(a[2]), "r"(a[3]), "r"(b[0]), "r"(b[1]));
}

__device__ __forceinline__ float ex2f(float x) {
    float y; asm("ex2.approx.ftz.f32 %0, %1;" : "=f"(y) : "f"(x)); return y;
}

__device__ __forceinline__ void bsplit(float v, __nv_bfloat16& hi, __nv_bfloat16& lo) {
    hi = __float2bfloat16_rn(v);
    lo = __float2bfloat16_rn(v - __bfloat162float(hi));
}
__device__ __forceinline__ uint32_t pack2(__nv_bfloat16 a, __nv_bfloat16 b) {
    __nv_bfloat162 t = __halves2bfloat162(a, b);
    return *reinterpret_cast<uint32_t*>(&t);
}

// ---------------------------------------------------------------------------
// Kernel A: convert x -> bf16 hi/lo
// ---------------------------------------------------------------------------
__global__ __launch_bounds__(256) void cvt_x_kernel(const float* __restrict__ x)
{
    int i = blockIdx.x * 256 + threadIdx.x;      // float4 index
    float4 v = ((const float4*)x)[i];
    __nv_bfloat16 h0, h1, h2, h3, l0, l1, l2, l3;
    bsplit(v.x, h0, l0); bsplit(v.y, h1, l1);
    bsplit(v.z, h2, l2); bsplit(v.w, h3, l3);
    uint2 uh, ul;
    uh.x = pack2(h0, h1); uh.y = pack2(h2, h3);
    ul.x = pack2(l0, l1); ul.y = pack2(l2, l3);
    ((uint2*)g_xhi)[i] = uh;
    ((uint2*)g_xlo)[i] = ul;
}

// ---------------------------------------------------------------------------
// Kernel B: convert + transpose weights
// ---------------------------------------------------------------------------
__global__ __launch_bounds__(256) void cvt_w_kernel(
    const float* __restrict__ Wq, const float* __restrict__ Wk,
    const float* __restrict__ Wv, const float* __restrict__ Wp)
{
    int gi = blockIdx.x * 256 + threadIdx.x;
    float v; size_t dst;
    if (gi < 18 * NW) {
        int g = gi / NW, rem = gi % NW;
        int k = rem / HS, n = rem % HS;
        int mat = g / HH, h = g % HH;
        const float* W = (mat == 0 ? Wq : (mat == 1 ? Wk : Wv));
        v = W[(size_t)h * CC * HS + (size_t)k * HS + n];
        dst = (size_t)g * NW + (size_t)n * CC + k;
    } else {
        int j = gi - 18 * NW;
        int k = j / CC, n = j % CC;
        v = Wp[(size_t)k * CC + n];
        dst = WP_OFF + (size_t)n * CC + k;
    }
    __nv_bfloat16 hi, lo;
    bsplit(v, hi, lo);
    g_wthi[dst] = hi;
    g_wtlo[dst] = lo;
}

// ---------------------------------------------------------------------------
// Kernel C: HMMA GEMM, D[128 x 64] = A[128 x 384] * B^T, bf16 2-way split.
// MODE 0: QKV  -> writes Q/K bf16 hi/lo [bh][t][d], V transposed [bh][d][t]
// MODE 1: proj -> d_out fp32 + bias
// ---------------------------------------------------------------------------
#define PAD 40   // bf16 elements per smem row (80 bytes; BK=32 -> 64B data + 16 pad)

template <int MODE>
__global__ __launch_bounds__(256) void gemm_hmma_kernel(
    const float* __restrict__ bp, float* __restrict__ out)
{
    __shared__ __nv_bfloat16 sAhi[128 * PAD];
    __shared__ __nv_bfloat16 sAlo[128 * PAD];
    __shared__ __nv_bfloat16 sBhi[64 * PAD];
    __shared__ __nv_bfloat16 sBlo[64 * PAD];

    const int tid = threadIdx.x;
    const int wid = tid >> 5, lane = tid & 31;
    const int wm = wid & 3, wn = wid >> 2;       // 4 x 2 warp grid
    const int m0 = blockIdx.x * 128;

    const __nv_bfloat16 *Ahi, *Alo, *Bhi, *Blo;
    int mat = 0, h = 0, n0 = 0;
    if (MODE == 0) {
        int g = blockIdx.y; mat = g / HH; h = g % HH;
        Ahi = g_xhi; Alo = g_xlo;
        Bhi = g_wthi + (size_t)g * NW; Blo = g_wtlo + (size_t)g * NW;
    } else {
        n0 = blockIdx.y * 64;
        Ahi = g_ohi; Alo = g_olo;
        Bhi = g_wthi + WP_OFF + (size_t)n0 * CC;
        Blo = g_wtlo + WP_OFF + (size_t)n0 * CC;
    }

    const int qq = lane >> 3, rr = lane & 7;
    const uint32_t aHiB = smem_u32(sAhi), aLoB = smem_u32(sAlo);
    const uint32_t bHiB = smem_u32(sBhi), bLoB = smem_u32(sBlo);
    const uint32_t aoff = (uint32_t)((wm * 32 + (qq & 1) * 8 + rr) * 80 + (qq >> 1) * 16);
    const uint32_t boff = (uint32_t)((wn * 32 + (qq >> 1) * 8 + rr) * 80 + (qq & 1) * 16);

    float c[2][4][4];
    #pragma unroll
    for (int i = 0; i < 2; i++)
        #pragma unroll
        for (int j = 0; j < 4; j++)
            #pragma unroll
            for (int k = 0; k < 4; k++) c[i][j][k] = 0.f;

    #pragma unroll 1
    for (int ch = 0; ch < CC / 32; ch++) {
        const int k0 = ch * 32;
        __syncthreads();

        #pragma unroll
        for (int i = 0; i < 2; i++) {
            int cid = tid + i * 256;
            int row = cid >> 2, cj = cid & 3;
            *(uint4*)(sAhi + row * PAD + cj * 8) =
                *(const uint4*)(Ahi + (size_t)(m0 + row) * CC + k0 + cj * 8);
            *(uint4*)(sAlo + row * PAD + cj * 8) =
                *(const uint4*)(Alo + (size_t)(m0 + row) * CC + k0 + cj * 8);
        }
        {
            int row = tid >> 2, cj = tid & 3;
            *(uint4*)(sBhi + row * PAD + cj * 8) =
                *(const uint4*)(Bhi + (size_t)row * CC + k0 + cj * 8);
            *(uint4*)(sBlo + row * PAD + cj * 8) =
                *(const uint4*)(Blo + (size_t)row * CC + k0 + cj * 8);
        }
        __syncthreads();

        #pragma unroll
        for (int ks = 0; ks < 2; ks++) {
            const uint32_t kb = ks * 32;
            uint32_t ah[2][4], al[2][4], bh[2][4], bl[2][4];
            #pragma unroll
            for (int mi = 0; mi < 2; mi++) {
                ldm_x4(ah[mi], aHiB + aoff + mi * (16 * 80) + kb);
                ldm_x4(al[mi], aLoB + aoff + mi * (16 * 80) + kb);
            }
            #pragma unroll
            for (int nt = 0; nt < 2; nt++) {
                ldm_x4(bh[nt], bHiB + boff + nt * (16 * 80) + kb);
                ldm_x4(bl[nt], bLoB + boff + nt * (16 * 80) + kb);
            }
            #pragma unroll
            for (int mi = 0; mi < 2; mi++)
                #pragma unroll
                for (int ni = 0; ni < 4; ni++)
                    mma16816(c[mi][ni], ah[mi], &bh[ni >> 1][(ni & 1) * 2]);
            #pragma unroll
            for (int mi = 0; mi < 2; mi++)
                #pragma unroll
                for (int ni = 0; ni < 4; ni++)
                    mma16816(c[mi][ni], ah[mi], &bl[ni >> 1][(ni & 1) * 2]);
            #pragma unroll
            for (int mi = 0; mi < 2; mi++)
                #pragma unroll
                for (int ni = 0; ni < 4; ni++)
                    mma16816(c[mi][ni], al[mi], &bh[ni >> 1][(ni & 1) * 2]);
        }
    }

    // ---- epilogue ----
    const int gr = lane >> 2, gc = (lane & 3) * 2;
    if (MODE == 0) {
        const int bhh_stride = TT * HS;
        #pragma unroll
        for (int mi = 0; mi < 2; mi++) {
            #pragma unroll
            for (int hc = 0; hc < 2; hc++) {
                int m = m0 + wm * 32 + mi * 16 + hc * 8 + gr;
                int b = m >> 8, t = m & (TT - 1);
                int bhh = b * HH + h;
                if (mat < 2) {
                    __nv_bfloat16* Hq = (mat == 0 ? g_qhi : g_khi)
                                        + (size_t)bhh * bhh_stride + (size_t)t * HS;
                    __nv_bfloat16* Lq = (mat == 0 ? g_qlo : g_klo)
                                        + (size_t)bhh * bhh_stride + (size_t)t * HS;
                    #pragma unroll
                    for (int ni = 0; ni < 4; ni++) {
                        int col = wn * 32 + ni * 8 + gc;
                        __nv_bfloat16 h0, h1, l0, l1;
                        bsplit(c[mi][ni][hc * 2], h0, l0);
                        bsplit(c[mi][ni][hc * 2 + 1], h1, l1);
                        *(uint32_t*)(Hq + col) = pack2(h0, h1);
                        *(uint32_t*)(Lq + col) = pack2(l0, l1);
                    }
                } else {
                    // V: transposed store [bh][d][t]
                    #pragma unroll
                    for (int ni = 0; ni < 4; ni++) {
                        int col = wn * 32 + ni * 8 + gc;
                        __nv_bfloat16 h0, h1, l0, l1;
                        bsplit(c[mi][ni][hc * 2], h0, l0);
                        bsplit(c[mi][ni][hc * 2 + 1], h1, l1);
                        size_t base = (size_t)bhh * HS * TT;
                        g_vthi[base + (size_t)col * TT + t] = h0;
                        g_vthi[base + (size_t)(col + 1) * TT + t] = h1;
                        g_vtlo[base + (size_t)col * TT + t] = l0;
                        g_vtlo[base + (size_t)(col + 1) * TT + t] = l1;
                    }
                }
            }
        }
    } else {
        #pragma unroll
        for (int mi = 0; mi < 2; mi++) {
            #pragma unroll
            for (int hc = 0; hc < 2; hc++) {
                int m = m0 + wm * 32 + mi * 16 + hc * 8 + gr;
                float* O = out + (size_t)m * CC + n0;
                #pragma unroll
                for (int ni = 0; ni < 4; ni++) {
                    int col = wn * 32 + ni * 8 + gc;
                    float2 bb = *(const float2*)(bp + n0 + col);
                    float2 v = make_float2(c[mi][ni][hc * 2] + bb.x,
                                           c[mi][ni][hc * 2 + 1] + bb.y);
                    *(float2*)(O + col) = v;
                }
            }
        }
    }
}

// ---------------------------------------------------------------------------
// Kernel D: HMMA flash attention.
// Block = 128 q-rows of one (b,h). 8 warps x 16 rows. K/V smem-resident.
// Q/K rows are 64 bf16 = 128 B data -> smem row stride 144 B (128 + 16 pad).
// V^T rows are 256 bf16 = 512 B data -> stride 528 B.
// ---------------------------------------------------------------------------
#define QSTR 144
#define VSTR 528
#define SQH 0
#define SQL 18432
#define SKH 36864
#define SKL 73728
#define SVH 110592
#define SVL 144384
#define ATTN_SMEM 178176

__global__ __launch_bounds__(256) void attn_hmma_kernel()
{
    extern __shared__ char sm[];
    const int tid = threadIdx.x;
    const int wid = tid >> 5, lane = tid & 31;
    const int bh = blockIdx.y;
    const int b = bh / HH, h = bh % HH;
    const int q0 = (int)blockIdx.x << 7;
    const int kmax = q0 + 128;

    // ---- cooperative loads ----
    {
        const uint4* gqh = (const uint4*)(g_qhi + ((size_t)bh * TT + q0) * HS);
        const uint4* gql = (const uint4*)(g_qlo + ((size_t)bh * TT + q0) * HS);
        #pragma unroll
        for (int i = 0; i < 4; i++) {
            int idx = tid + i * 256;
            int row = idx >> 3, cj = idx & 7;
            *(uint4*)(sm + SQH + row * QSTR + cj * 16) = gqh[idx];
            *(uint4*)(sm + SQL + row * QSTR + cj * 16) = gql[idx];
        }
        const uint4* gkh = (const uint4*)(g_khi + (size_t)bh * TT * HS);
        const uint4* gkl = (const uint4*)(g_klo + (size_t)bh * TT * HS);
        for (int idx = tid; idx < kmax * 8; idx += 256) {
            int row = idx >> 3, cj = idx & 7;
            *(uint4*)(sm + SKH + row * QSTR + cj * 16) = gkh[idx];
            *(uint4*)(sm + SKL + row * QSTR + cj * 16) = gkl[idx];
        }
        const uint4* gvh = (const uint4*)(g_vthi + (size_t)bh * HS * TT);
        const uint4* gvl = (const uint4*)(g_vtlo + (size_t)bh * HS * TT);
        const int cw = kmax >> 3;   // uint4 chunks per d-row (16 or 32)
        for (int idx = tid; idx < 64 * cw; idx += 256) {
            int row = (kmax == 256) ? (idx >> 5) : (idx >> 4);
            int cj = idx - row * cw;
            *(uint4*)(sm + SVH + row * VSTR + cj * 16) = gvh[row * 32 + cj];
            *(uint4*)(sm + SVL + row * VSTR + cj * 16) = gvl[row * 32 + cj];
        }
    }
    __syncthreads();

    const int qq = lane >> 3, rr = lane & 7;
    const uint32_t qhB = smem_u32(sm + SQH), qlB = smem_u32(sm + SQL);
    const uint32_t khB = smem_u32(sm + SKH), klB = smem_u32(sm + SKL);
    const uint32_t vhB = smem_u32(sm + SVH), vlB = smem_u32(sm + SVL);
    const uint32_t aoff = (uint32_t)((wid * 16 + (qq & 1) * 8 + rr) * QSTR + (qq >> 1) * 16);
    const uint32_t krow = (uint32_t)((qq >> 1) * 8 + rr);
    const uint32_t kcol = (uint32_t)((qq & 1) * 16);

    // Q fragments resident
    uint32_t qh[4][4], ql[4][4];
    #pragma unroll
    for (int ks = 0; ks < 4; ks++) {
        ldm_x4(qh[ks], qhB + aoff + ks * 32);
        ldm_x4(ql[ks], qlB + aoff + ks * 32);
    }

    float o[8][4];
    #pragma unroll
    for (int i = 0; i < 8; i++)
        #pragma unroll
        for (int j = 0; j < 4; j++) o[i][j] = 0.f;

    float m0 = -1e30f, m1 = -1e30f, l0 = 0.f, l1 = 0.f;
    const int gr = lane >> 2, gc = (lane & 3) * 2;
    const int row0 = q0 + wid * 16 + gr;
    const int rmaxw = q0 + wid * 16 + 15;   // warp-uniform
    const float scl = 0.125f * 1.44269504088896f;   // fold log2e into scale

    for (int cb = 0; cb <= rmaxw; cb += 64) {
        float s[8][4];
        #pragma unroll
        for (int i = 0; i < 8; i++)
            #pragma unroll
            for (int j = 0; j < 4; j++) s[i][j] = 0.f;

        // ---- S = Q @ K^T (3-pass split) ----
        #pragma unroll
        for (int ks = 0; ks < 4; ks++) {
            uint32_t kh[4][4], kl[4][4];
            #pragma unroll
            for (int nt = 0; nt < 4; nt++) {
                uint32_t ro = (uint32_t)(cb + nt * 16 + krow) * QSTR + kcol + ks * 32;
                ldm_x4(kh[nt], khB + ro);
                ldm_x4(kl[nt], klB + ro);
            }
            #pragma unroll
            for (int ni = 0; ni < 8; ni++)
                mma16816(s[ni], qh[ks], &kh[ni >> 1][(ni & 1) * 2]);
            #pragma unroll
            for (int ni = 0; ni < 8; ni++)
                mma16816(s[ni], qh[ks], &kl[ni >> 1][(ni & 1) * 2]);
            #pragma unroll
            for (int ni = 0; ni < 8; ni++)
                mma16816(s[ni], ql[ks], &kh[ni >> 1][(ni & 1) * 2]);
        }

        // ---- scale + causal mask ----
        #pragma unroll
        for (int ni = 0; ni < 8; ni++) {
            int col = cb + ni * 8 + gc;
            s[ni][0] = (col     <= row0)     ? s[ni][0] * scl : -1e30f;
            s[ni][1] = (col + 1 <= row0)     ? s[ni][1] * scl : -1e30f;
            s[ni][2] = (col     <= row0 + 8) ? s[ni][2] * scl : -1e30f;
            s[ni][3] = (col + 1 <= row0 + 8) ? s[ni][3] * scl : -1e30f;
        }

        // ---- online softmax (base-2) ----
        float a0 = -1e30f, a1 = -1e30f;
        #pragma unroll
        for (int ni = 0; ni < 8; ni++) {
            a0 = fmaxf(a0, fmaxf(s[ni][0], s[ni][1]));
            a1 = fmaxf(a1, fmaxf(s[ni][2], s[ni][3]));
        }
        a0 = fmaxf(a0, __shfl_xor_sync(0xffffffffu, a0, 1));
        a0 = fmaxf(a0, __shfl_xor_sync(0xffffffffu, a0, 2));
        a1 = fmaxf(a1, __shfl_xor_sync(0xffffffffu, a1, 1));
        a1 = fmaxf(a1, __shfl_xor_sync(0xffffffffu, a1, 2));
        float mn0 = fmaxf(m0, a0), mn1 = fmaxf(m1, a1);
        float c0 = ex2f(m0 - mn0), c1 = ex2f(m1 - mn1);
        float ls0 = 0.f, ls1 = 0.f;
        #pragma unroll
        for (int ni = 0; ni < 8; ni++) {
            s[ni][0] = ex2f(s[ni][0] - mn0); ls0 += s[ni][0];
            s[ni][1] = ex2f(s[ni][1] - mn0); ls0 += s[ni][1];
            s[ni][2] = ex2f(s[ni][2] - mn1); ls1 += s[ni][2];
            s[ni][3] = ex2f(s[ni][3] - mn1); ls1 += s[ni][3];
        }
        l0 = l0 * c0 + ls0;
        l1 = l1 * c1 + ls1;
        m0 = mn0; m1 = mn1;
        #pragma unroll
        for (int ni = 0; ni < 8; ni++) {
            o[ni][0] *= c0; o[ni][1] *= c0;
            o[ni][2] *= c1; o[ni][3] *= c1;
        }

        // ---- O += P @ V (3-pass split; V^T resident so B uses plain ldmatrix) ----
        #pragma unroll
        for (int g = 0; g < 4; g++) {
            uint32_t ph[4], pl[4];
            {
                __nv_bfloat16 x0, x1, y0, y1;
                bsplit(s[2*g][0], x0, y0); bsplit(s[2*g][1], x1, y1);
                ph[0] = pack2(x0, x1); pl[0] = pack2(y0, y1);
                bsplit(s[2*g][2], x0, y0); bsplit(s[2*g][3], x1, y1);
                ph[1] = pack2(x0, x1); pl[1] = pack2(y0, y1);
                bsplit(s[2*g+1][0], x0, y0); bsplit(s[2*g+1][1], x1, y1);
                ph[2] = pack2(x0, x1); pl[2] = pack2(y0, y1);
                bsplit(s[2*g+1][2], x0, y0); bsplit(s[2*g+1][3], x1, y1);
                ph[3] = pack2(x0, x1); pl[3] = pack2(y0, y1);
            }
            #pragma unroll
            for (int nt = 0; nt < 4; nt++) {
                uint32_t ro = (uint32_t)(nt * 16 + krow) * VSTR + (uint32_t)cb * 2
                              + g * 32 + kcol;
                uint32_t vh[4], vl[4];
                ldm_x4(vh, vhB + ro);
                ldm_x4(vl, vlB + ro);
                mma16816(o[nt * 2],     ph, &vh[0]);
                mma16816(o[nt * 2 + 1], ph, &vh[2]);
                mma16816(o[nt * 2],     ph, &vl[0]);
                mma16816(o[nt * 2 + 1], ph, &vl[2]);
                mma16816(o[nt * 2],     pl, &vh[0]);
                mma16816(o[nt * 2 + 1], pl, &vh[2]);
            }
        }
    }

    // ---- finalize ----
    l0 += __shfl_xor_sync(0xffffffffu, l0, 1);
    l0 += __shfl_xor_sync(0xffffffffu, l0, 2);
    l1 += __shfl_xor_sync(0xffffffffu, l1, 1);
    l1 += __shfl_xor_sync(0xffffffffu, l1, 2);
    float i0 = 1.f / l0, i1 = 1.f / l1;

    size_t base0 = ((size_t)b * TT + row0) * CC + h * HS;
    size_t base1 = ((size_t)b * TT + row0 + 8) * CC + h * HS;
    #pragma unroll
    for (int ni = 0; ni < 8; ni++) {
        int d = ni * 8 + gc;
        __nv_bfloat16 h0, h1, l0b, l1b;
        bsplit(o[ni][0] * i0, h0, l0b);
        bsplit(o[ni][1] * i0, h1, l1b);
        *(uint32_t*)(g_ohi + base0 + d) = pack2(h0, h1);
        *(uint32_t*)(g_olo + base0 + d) = pack2(l0b, l1b);
        bsplit(o[ni][2] * i1, h0, l0b);
        bsplit(o[ni][3] * i1, h1, l1b);
        *(uint32_t*)(g_ohi + base1 + d) = pack2(h0, h1);
        *(uint32_t*)(g_olo + base1 + d) = pack2(l0b, l1b);
    }
}

// ---------------------------------------------------------------------------
extern "C" void kernel_launch(void* const* d_in, const int* in_sizes, int n_in,
                              void* d_out, int out_size)
{
    const float* x  = (const float*)d_in[0];
    const float* Wq = (const float*)d_in[1];
    const float* Wk = (const float*)d_in[2];
    const float* Wv = (const float*)d_in[3];
    const float* Wp = (const float*)d_in[4];
    const float* bp = (const float*)d_in[5];
    float* out = (float*)d_out;

    cudaFuncSetAttribute(attn_hmma_kernel,
                         cudaFuncAttributeMaxDynamicSharedMemorySize, ATTN_SMEM);

    cvt_x_kernel<<<(MM * CC / 4) / 256, 256>>>(x);
    cvt_w_kernel<<<(18 * NW + CC * CC) / 256, 256>>>(Wq, Wk, Wv, Wp);
    gemm_hmma_kernel<0><<<dim3(MM / 128, 18), 256>>>(nullptr, nullptr);
    attn_hmma_kernel<<<dim3(2, BB * HH), 256, ATTN_SMEM>>>();
    gemm_hmma_kernel<1><<<dim3(MM / 128, CC / 64), 256>>>(bp, out);
}

// round 10
// speedup vs baseline: 2.9721x; 1.3518x over previous
#include <cuda_runtime.h>
#include <cuda_fp16.h>
#include <cstdint>

// Problem constants
#define BB 128
#define TT 256
#define CC 384
#define HH 6
#define HS 64
#define MM (BB*TT)       // 32768 rows
#define NW 24576         // 64*384, one head's transposed weight
#define WP_OFF (18*NW)   // offset of Wp^T inside g_wt arrays

// ---------------------------------------------------------------------------
// Scratch (device globals; no allocations allowed)  — all fp16 now
// ---------------------------------------------------------------------------
__device__ __half g_xh[(size_t)MM*CC];                // x, fp16 (hi only)
__device__ __half g_wth[WP_OFF + CC*CC];              // weights^T hi
__device__ __half g_wtl[WP_OFF + CC*CC];              // weights^T lo
__device__ __half g_qh[(size_t)BB*HH*TT*HS];          // [bh][t][d]
__device__ __half g_ql[(size_t)BB*HH*TT*HS];
__device__ __half g_kh[(size_t)BB*HH*TT*HS];
__device__ __half g_kl[(size_t)BB*HH*TT*HS];
__device__ __half g_vh[(size_t)BB*HH*TT*HS];          // [bh][t][d] (natural)
__device__ __half g_vl[(size_t)BB*HH*TT*HS];
__device__ __half g_oh[(size_t)MM*CC];                // attention out hi
__device__ __half g_ol[(size_t)MM*CC];                // attention out lo

// ---------------------------------------------------------------------------
// Helpers
// ---------------------------------------------------------------------------
__device__ __forceinline__ uint32_t smem_u32(const void* p) {
    uint32_t a;
    asm("{ .reg .u64 t; cvta.to.shared.u64 t, %1; cvt.u32.u64 %0, t; }"
        : "=r"(a) : "l"(p));
    return a;
}

__device__ __forceinline__ void ldm_x4(uint32_t* r, uint32_t addr) {
    asm volatile("ldmatrix.sync.aligned.m8n8.x4.shared.b16 {%0,%1,%2,%3}, [%4];"
                 : "=r"(r[0]), "=r"(r[1]), "=r"(r[2]), "=r"(r[3]) : "r"(addr));
}
__device__ __forceinline__ void ldm_x4t(uint32_t* r, uint32_t addr) {
    asm volatile("ldmatrix.sync.aligned.m8n8.x4.trans.shared.b16 {%0,%1,%2,%3}, [%4];"
                 : "=r"(r[0]), "=r"(r[1]), "=r"(r[2]), "=r"(r[3]) : "r"(addr));
}

__device__ __forceinline__ void mma16816(float* c, const uint32_t* a, const uint32_t* b) {
    asm volatile(
        "mma.sync.aligned.m16n8k16.row.col.f32.f16.f16.f32 "
        "{%0,%1,%2,%3}, {%4,%5,%6,%7}, {%8,%9}, {%0,%1,%2,%3};"
        : "+f"(c[0]), "+f"(c[1]), "+f"(c[2]), "+f"(c[3])
        : "r"(a[0]), "r"(a[1]), "r"(a[2]), "r"(a[3]), "r"(b[0]), "r"(b[1]));
}

__device__ __forceinline__ float ex2f(float x) {
    float y; asm("ex2.approx.ftz.f32 %0, %1;" : "=f"(y) : "f"(x)); return y;
}

__device__ __forceinline__ void hsplit(float v, __half& hi, __half& lo) {
    hi = __float2half_rn(v);
    lo = __float2half_rn(v - __half2float(hi));
}
__device__ __forceinline__ uint32_t pack2(__half a, __half b) {
    __half2 t = __halves2half2(a, b);
    return *reinterpret_cast<uint32_t*>(&t);
}

__device__ __forceinline__ void cpasync16(uint32_t d, const void* s) {
    asm volatile("cp.async.cg.shared.global [%0], [%1], 16;" :: "r"(d), "l"(s));
}
#define CP_COMMIT() asm volatile("cp.async.commit_group;" ::: "memory")
#define CP_WAIT0()  asm volatile("cp.async.wait_group 0;" ::: "memory")

// ---------------------------------------------------------------------------
// Kernel A: convert x -> fp16 (hi only; 2-pass QKV uses exact-on-quantized-x)
// ---------------------------------------------------------------------------
__global__ __launch_bounds__(256) void cvt_x_kernel(const float* __restrict__ x)
{
    int i = blockIdx.x * 256 + threadIdx.x;      // float4 index
    float4 v = ((const float4*)x)[i];
    uint2 u;
    u.x = pack2(__float2half_rn(v.x), __float2half_rn(v.y));
    u.y = pack2(__float2half_rn(v.z), __float2half_rn(v.w));
    ((uint2*)g_xh)[i] = u;
}

// ---------------------------------------------------------------------------
// Kernel B: convert + transpose weights -> fp16 hi/lo
// ---------------------------------------------------------------------------
__global__ __launch_bounds__(256) void cvt_w_kernel(
    const float* __restrict__ Wq, const float* __restrict__ Wk,
    const float* __restrict__ Wv, const float* __restrict__ Wp)
{
    int gi = blockIdx.x * 256 + threadIdx.x;
    float v; size_t dst;
    if (gi < 18 * NW) {
        int g = gi / NW, rem = gi % NW;
        int k = rem / HS, n = rem % HS;
        int mat = g / HH, h = g % HH;
        const float* W = (mat == 0 ? Wq : (mat == 1 ? Wk : Wv));
        v = W[(size_t)h * CC * HS + (size_t)k * HS + n];
        dst = (size_t)g * NW + (size_t)n * CC + k;
    } else {
        int j = gi - 18 * NW;
        int k = j / CC, n = j % CC;
        v = Wp[(size_t)k * CC + n];
        dst = WP_OFF + (size_t)n * CC + k;
    }
    __half hi, lo;
    hsplit(v, hi, lo);
    g_wth[dst] = hi;
    g_wtl[dst] = lo;
}

// ---------------------------------------------------------------------------
// Kernel C: HMMA GEMM, 128x128 output tile, BK=64, 2-stage cp.async pipeline.
// MODE 0 (PASSES=2): QKV.  D = xh * W^T via {xh*wh + xh*wl}. A tile = hi only.
//   grid (256, 9); n-tile spans 2 head-groups; warp n-range = one group.
//   Epilogue -> Q/K/V fp16 hi/lo at [bh][t][d].
// MODE 1 (PASSES=3): proj. D = O * Wp^T via {oh*wh + oh*wl + ol*wh} + bias.
// Block 256 thr = 8 warps (4m x 2n), warp tile 32x64.
// smem rows: 64 halves = 128B data + 16 pad = 144B stride.
// ---------------------------------------------------------------------------
#define GSTR 144
#define GBUF 18432            // 128 rows * 144B, one tile buffer

template <int MODE, int PASSES>
__global__ __launch_bounds__(256) void gemm_kernel(
    const float* __restrict__ bp, float* __restrict__ out)
{
    extern __shared__ char smg[];
    const int tid = threadIdx.x;
    const int wid = tid >> 5, lane = tid & 31;
    const int wm = wid & 3, wn = wid >> 2;
    const int m0 = blockIdx.x * 128, n0 = blockIdx.y * 128;

    const __half *Ah, *Al = nullptr, *Bh, *Bl;
    if (MODE == 0) {
        Ah = g_xh;
        Bh = g_wth + (size_t)n0 * CC;
        Bl = g_wtl + (size_t)n0 * CC;
    } else {
        Ah = g_oh; Al = g_ol;
        Bh = g_wth + WP_OFF + (size_t)n0 * CC;
        Bl = g_wtl + WP_OFF + (size_t)n0 * CC;
    }

    const uint32_t base = smem_u32(smg);
    const uint32_t AH = base, BH = base + 2 * GBUF, BL = base + 4 * GBUF;
    const uint32_t ALo = base + 6 * GBUF;     // only PASSES==3

    auto prefetch = [&](int st, int c) {
        const int k0 = c * 64;
        #pragma unroll
        for (int i = 0; i < 4; i++) {
            int idx = i * 256 + tid;
            int row = idx >> 3, cj = idx & 7;
            uint32_t so = (uint32_t)(st * GBUF + row * GSTR + cj * 16);
            cpasync16(AH + so, Ah + (size_t)(m0 + row) * CC + k0 + cj * 8);
            if (PASSES == 3)
                cpasync16(ALo + so, Al + (size_t)(m0 + row) * CC + k0 + cj * 8);
            cpasync16(BH + so, Bh + (size_t)row * CC + k0 + cj * 8);
            cpasync16(BL + so, Bl + (size_t)row * CC + k0 + cj * 8);
        }
    };

    const int qq = lane >> 3, rr = lane & 7;
    const uint32_t aoff = (uint32_t)((wm * 32 + (qq & 1) * 8 + rr) * GSTR + (qq >> 1) * 16);
    const uint32_t boff = (uint32_t)((wn * 64 + (qq >> 1) * 8 + rr) * GSTR + (qq & 1) * 16);

    float c[2][8][4];
    #pragma unroll
    for (int i = 0; i < 2; i++)
        #pragma unroll
        for (int j = 0; j < 8; j++)
            #pragma unroll
            for (int k = 0; k < 4; k++) c[i][j][k] = 0.f;

    prefetch(0, 0);
    CP_COMMIT();

    #pragma unroll 1
    for (int ch = 0; ch < 6; ch++) {
        CP_WAIT0();
        __syncthreads();
        if (ch < 5) { prefetch((ch + 1) & 1, ch + 1); CP_COMMIT(); }

        const uint32_t st = (uint32_t)((ch & 1) * GBUF);
        #pragma unroll
        for (int ks = 0; ks < 4; ks++) {
            const uint32_t kb = ks * 32;
            uint32_t a_h[2][4], a_l[2][4], b_h[4][4], b_l[4][4];
            #pragma unroll
            for (int mi = 0; mi < 2; mi++) {
                ldm_x4(a_h[mi], AH + st + aoff + mi * (16 * GSTR) + kb);
                if (PASSES == 3)
                    ldm_x4(a_l[mi], ALo + st + aoff + mi * (16 * GSTR) + kb);
            }
            #pragma unroll
            for (int nt = 0; nt < 4; nt++) {
                ldm_x4(b_h[nt], BH + st + boff + nt * (16 * GSTR) + kb);
                ldm_x4(b_l[nt], BL + st + boff + nt * (16 * GSTR) + kb);
            }
            #pragma unroll
            for (int mi = 0; mi < 2; mi++)
                #pragma unroll
                for (int ni = 0; ni < 8; ni++)
                    mma16816(c[mi][ni], a_h[mi], &b_h[ni >> 1][(ni & 1) * 2]);
            #pragma unroll
            for (int mi = 0; mi < 2; mi++)
                #pragma unroll
                for (int ni = 0; ni < 8; ni++)
                    mma16816(c[mi][ni], a_h[mi], &b_l[ni >> 1][(ni & 1) * 2]);
            if (PASSES == 3) {
                #pragma unroll
                for (int mi = 0; mi < 2; mi++)
                    #pragma unroll
                    for (int ni = 0; ni < 8; ni++)
                        mma16816(c[mi][ni], a_l[mi], &b_h[ni >> 1][(ni & 1) * 2]);
            }
        }
    }

    // ---- epilogue ----
    const int gr = lane >> 2, gc = (lane & 3) * 2;
    if (MODE == 0) {
        // warp covers cols [wn*64, wn*64+64) of tile -> exactly one (mat,head)
        int g = blockIdx.y * 2 + wn;          // 0..17
        int mat = g / HH, h = g % HH;
        __half *H, *L;
        if (mat == 0)      { H = g_qh; L = g_ql; }
        else if (mat == 1) { H = g_kh; L = g_kl; }
        else               { H = g_vh; L = g_vl; }
        #pragma unroll
        for (int mi = 0; mi < 2; mi++) {
            #pragma unroll
            for (int hc = 0; hc < 2; hc++) {
                int m = m0 + wm * 32 + mi * 16 + hc * 8 + gr;
                int b = m >> 8, t = m & (TT - 1);
                size_t rowb = ((size_t)(b * HH + h) * TT + t) * HS;
                #pragma unroll
                for (int ni = 0; ni < 8; ni++) {
                    int d = ni * 8 + gc;
                    __half h0, h1, l0, l1;
                    hsplit(c[mi][ni][hc * 2],     h0, l0);
                    hsplit(c[mi][ni][hc * 2 + 1], h1, l1);
                    *(uint32_t*)(H + rowb + d) = pack2(h0, h1);
                    *(uint32_t*)(L + rowb + d) = pack2(l0, l1);
                }
            }
        }
    } else {
        #pragma unroll
        for (int mi = 0; mi < 2; mi++) {
            #pragma unroll
            for (int hc = 0; hc < 2; hc++) {
                int m = m0 + wm * 32 + mi * 16 + hc * 8 + gr;
                float* O = out + (size_t)m * CC + n0;
                #pragma unroll
                for (int ni = 0; ni < 8; ni++) {
                    int col = wn * 64 + ni * 8 + gc;
                    float2 bb = *(const float2*)(bp + n0 + col);
                    float2 v = make_float2(c[mi][ni][hc * 2] + bb.x,
                                           c[mi][ni][hc * 2 + 1] + bb.y);
                    *(float2*)(O + col) = v;
                }
            }
        }
    }
}

// ---------------------------------------------------------------------------
// Kernel D: HMMA flash attention (fp16).
// Block = 128 q-rows of one (b,h). 8 warps x 16 rows. K/V smem-resident.
// Q/K/V rows: 64 halves = 128B data -> stride 144B.
// S  = qh*kh + qh*kl + ql*kh ; PV = ph*vh + ph*vl + pl*vh.
// V stored [t][d]; PV B-fragments via ldmatrix.x4.trans.
// ---------------------------------------------------------------------------
#define QSTR 144
#define SQH 0
#define SQL 18432
#define SKH 36864
#define SKL 73728
#define SVH 110592
#define SVL 147456
#define ATTN_SMEM 184320

__global__ __launch_bounds__(256) void attn_hmma_kernel()
{
    extern __shared__ char sm[];
    const int tid = threadIdx.x;
    const int wid = tid >> 5, lane = tid & 31;
    const int bh = blockIdx.y;
    const int b = bh / HH, h = bh % HH;
    const int q0 = (int)blockIdx.x << 7;
    const int kmax = q0 + 128;

    // ---- cooperative loads ----
    {
        const uint4* gqh = (const uint4*)(g_qh + ((size_t)bh * TT + q0) * HS);
        const uint4* gql = (const uint4*)(g_ql + ((size_t)bh * TT + q0) * HS);
        #pragma unroll
        for (int i = 0; i < 4; i++) {
            int idx = tid + i * 256;
            int row = idx >> 3, cj = idx & 7;
            *(uint4*)(sm + SQH + row * QSTR + cj * 16) = gqh[idx];
            *(uint4*)(sm + SQL + row * QSTR + cj * 16) = gql[idx];
        }
        const uint4* gkh = (const uint4*)(g_kh + (size_t)bh * TT * HS);
        const uint4* gkl = (const uint4*)(g_kl + (size_t)bh * TT * HS);
        const uint4* gvh = (const uint4*)(g_vh + (size_t)bh * TT * HS);
        const uint4* gvl = (const uint4*)(g_vl + (size_t)bh * TT * HS);
        for (int idx = tid; idx < kmax * 8; idx += 256) {
            int row = idx >> 3, cj = idx & 7;
            *(uint4*)(sm + SKH + row * QSTR + cj * 16) = gkh[idx];
            *(uint4*)(sm + SKL + row * QSTR + cj * 16) = gkl[idx];
            *(uint4*)(sm + SVH + row * QSTR + cj * 16) = gvh[idx];
            *(uint4*)(sm + SVL + row * QSTR + cj * 16) = gvl[idx];
        }
    }
    __syncthreads();

    const int qq = lane >> 3, rr = lane & 7;
    const uint32_t qhB = smem_u32(sm + SQH), qlB = smem_u32(sm + SQL);
    const uint32_t khB = smem_u32(sm + SKH), klB = smem_u32(sm + SKL);
    const uint32_t vhB = smem_u32(sm + SVH), vlB = smem_u32(sm + SVL);
    const uint32_t aoff = (uint32_t)((wid * 16 + (qq & 1) * 8 + rr) * QSTR + (qq >> 1) * 16);
    const uint32_t krow = (uint32_t)((qq >> 1) * 8 + rr);     // B non-trans (K)
    const uint32_t kcol = (uint32_t)((qq & 1) * 16);
    const uint32_t vrow = (uint32_t)((qq & 1) * 8 + rr);      // B trans (V)
    const uint32_t vcol = (uint32_t)((qq >> 1) * 16);         // bytes (8 halves)

    // Q fragments resident
    uint32_t qh[4][4], ql[4][4];
    #pragma unroll
    for (int ks = 0; ks < 4; ks++) {
        ldm_x4(qh[ks], qhB + aoff + ks * 32);
        ldm_x4(ql[ks], qlB + aoff + ks * 32);
    }

    float o[8][4];
    #pragma unroll
    for (int i = 0; i < 8; i++)
        #pragma unroll
        for (int j = 0; j < 4; j++) o[i][j] = 0.f;

    float m0 = -1e30f, m1 = -1e30f, l0 = 0.f, l1 = 0.f;
    const int gr = lane >> 2, gc = (lane & 3) * 2;
    const int row0 = q0 + wid * 16 + gr;
    const int rmaxw = q0 + wid * 16 + 15;   // warp-uniform
    const float scl = 0.125f * 1.44269504088896f;   // fold log2e into scale

    for (int cb = 0; cb <= rmaxw; cb += 64) {
        float s[8][4];
        #pragma unroll
        for (int i = 0; i < 8; i++)
            #pragma unroll
            for (int j = 0; j < 4; j++) s[i][j] = 0.f;

        // ---- S = Q @ K^T (3-pass) ----
        #pragma unroll
        for (int ks = 0; ks < 4; ks++) {
            uint32_t kh[4][4], kl[4][4];
            #pragma unroll
            for (int nt = 0; nt < 4; nt++) {
                uint32_t ro = (uint32_t)(cb + nt * 16 + krow) * QSTR + kcol + ks * 32;
                ldm_x4(kh[nt], khB + ro);
                ldm_x4(kl[nt], klB + ro);
            }
            #pragma unroll
            for (int ni = 0; ni < 8; ni++)
                mma16816(s[ni], qh[ks], &kh[ni >> 1][(ni & 1) * 2]);
            #pragma unroll
            for (int ni = 0; ni < 8; ni++)
                mma16816(s[ni], qh[ks], &kl[ni >> 1][(ni & 1) * 2]);
            #pragma unroll
            for (int ni = 0; ni < 8; ni++)
                mma16816(s[ni], ql[ks], &kh[ni >> 1][(ni & 1) * 2]);
        }

        // ---- scale + causal mask ----
        #pragma unroll
        for (int ni = 0; ni < 8; ni++) {
            int col = cb + ni * 8 + gc;
            s[ni][0] = (col     <= row0)     ? s[ni][0] * scl : -1e30f;
            s[ni][1] = (col + 1 <= row0)     ? s[ni][1] * scl : -1e30f;
            s[ni][2] = (col     <= row0 + 8) ? s[ni][2] * scl : -1e30f;
            s[ni][3] = (col + 1 <= row0 + 8) ? s[ni][3] * scl : -1e30f;
        }

        // ---- online softmax (base-2) ----
        float a0 = -1e30f, a1 = -1e30f;
        #pragma unroll
        for (int ni = 0; ni < 8; ni++) {
            a0 = fmaxf(a0, fmaxf(s[ni][0], s[ni][1]));
            a1 = fmaxf(a1, fmaxf(s[ni][2], s[ni][3]));
        }
        a0 = fmaxf(a0, __shfl_xor_sync(0xffffffffu, a0, 1));
        a0 = fmaxf(a0, __shfl_xor_sync(0xffffffffu, a0, 2));
        a1 = fmaxf(a1, __shfl_xor_sync(0xffffffffu, a1, 1));
        a1 = fmaxf(a1, __shfl_xor_sync(0xffffffffu, a1, 2));
        float mn0 = fmaxf(m0, a0), mn1 = fmaxf(m1, a1);
        float c0 = ex2f(m0 - mn0), c1 = ex2f(m1 - mn1);
        float ls0 = 0.f, ls1 = 0.f;
        #pragma unroll
        for (int ni = 0; ni < 8; ni++) {
            s[ni][0] = ex2f(s[ni][0] - mn0); ls0 += s[ni][0];
            s[ni][1] = ex2f(s[ni][1] - mn0); ls0 += s[ni][1];
            s[ni][2] = ex2f(s[ni][2] - mn1); ls1 += s[ni][2];
            s[ni][3] = ex2f(s[ni][3] - mn1); ls1 += s[ni][3];
        }
        l0 = l0 * c0 + ls0;
        l1 = l1 * c1 + ls1;
        m0 = mn0; m1 = mn1;
        #pragma unroll
        for (int ni = 0; ni < 8; ni++) {
            o[ni][0] *= c0; o[ni][1] *= c0;
            o[ni][2] *= c1; o[ni][3] *= c1;
        }

        // ---- O += P @ V (3-pass; B-frags via ldmatrix.trans on [t][d] V) ----
        #pragma unroll
        for (int g = 0; g < 4; g++) {
            uint32_t ph[4], pl[4];
            {
                __half x0, x1, y0, y1;
                hsplit(s[2*g][0], x0, y0); hsplit(s[2*g][1], x1, y1);
                ph[0] = pack2(x0, x1); pl[0] = pack2(y0, y1);
                hsplit(s[2*g][2], x0, y0); hsplit(s[2*g][3], x1, y1);
                ph[1] = pack2(x0, x1); pl[1] = pack2(y0, y1);
                hsplit(s[2*g+1][0], x0, y0); hsplit(s[2*g+1][1], x1, y1);
                ph[2] = pack2(x0, x1); pl[2] = pack2(y0, y1);
                hsplit(s[2*g+1][2], x0, y0); hsplit(s[2*g+1][3], x1, y1);
                ph[3] = pack2(x0, x1); pl[3] = pack2(y0, y1);
            }
            #pragma unroll
            for (int nt = 0; nt < 4; nt++) {
                // matrices: (s0-7,d0-7)(s8-15,d0-7)(s0-7,d8-15)(s8-15,d8-15)
                uint32_t ro = (uint32_t)(cb + g * 16 + vrow) * QSTR + nt * 32 + vcol;
                uint32_t vh[4], vl[4];
                ldm_x4t(vh, vhB + ro);
                ldm_x4t(vl, vlB + ro);
                mma16816(o[nt * 2],     ph, &vh[0]);
                mma16816(o[nt * 2 + 1], ph, &vh[2]);
                mma16816(o[nt * 2],     ph, &vl[0]);
                mma16816(o[nt * 2 + 1], ph, &vl[2]);
                mma16816(o[nt * 2],     pl, &vh[0]);
                mma16816(o[nt * 2 + 1], pl, &vh[2]);
            }
        }
    }

    // ---- finalize ----
    l0 += __shfl_xor_sync(0xffffffffu, l0, 1);
    l0 += __shfl_xor_sync(0xffffffffu, l0, 2);
    l1 += __shfl_xor_sync(0xffffffffu, l1, 1);
    l1 += __shfl_xor_sync(0xffffffffu, l1, 2);
    float i0 = 1.f / l0, i1 = 1.f / l1;

    size_t base0 = ((size_t)b * TT + row0) * CC + h * HS;
    size_t base1 = ((size_t)b * TT + row0 + 8) * CC + h * HS;
    #pragma unroll
    for (int ni = 0; ni < 8; ni++) {
        int d = ni * 8 + gc;
        __half h0, h1, l0b, l1b;
        hsplit(o[ni][0] * i0, h0, l0b);
        hsplit(o[ni][1] * i0, h1, l1b);
        *(uint32_t*)(g_oh + base0 + d) = pack2(h0, h1);
        *(uint32_t*)(g_ol + base0 + d) = pack2(l0b, l1b);
        hsplit(o[ni][2] * i1, h0, l0b);
        hsplit(o[ni][3] * i1, h1, l1b);
        *(uint32_t*)(g_oh + base1 + d) = pack2(h0, h1);
        *(uint32_t*)(g_ol + base1 + d) = pack2(l0b, l1b);
    }
}

// ---------------------------------------------------------------------------
extern "C" void kernel_launch(void* const* d_in, const int* in_sizes, int n_in,
                              void* d_out, int out_size)
{
    const float* x  = (const float*)d_in[0];
    const float* Wq = (const float*)d_in[1];
    const float* Wk = (const float*)d_in[2];
    const float* Wv = (const float*)d_in[3];
    const float* Wp = (const float*)d_in[4];
    const float* bp = (const float*)d_in[5];
    float* out = (float*)d_out;

    cudaFuncSetAttribute(gemm_kernel<0, 2>,
                         cudaFuncAttributeMaxDynamicSharedMemorySize, 6 * GBUF);
    cudaFuncSetAttribute(gemm_kernel<1, 3>,
                         cudaFuncAttributeMaxDynamicSharedMemorySize, 8 * GBUF);
    cudaFuncSetAttribute(attn_hmma_kernel,
                         cudaFuncAttributeMaxDynamicSharedMemorySize, ATTN_SMEM);

    cvt_x_kernel<<<(MM * CC / 4) / 256, 256>>>(x);
    cvt_w_kernel<<<(18 * NW + CC * CC) / 256, 256>>>(Wq, Wk, Wv, Wp);
    gemm_kernel<0, 2><<<dim3(MM / 128, 9), 256, 6 * GBUF>>>(nullptr, nullptr);
    attn_hmma_kernel<<<dim3(2, BB * HH), 256, ATTN_SMEM>>>();
    gemm_kernel<1, 3><<<dim3(MM / 128, CC / 64 / 2), 256, 8 * GBUF>>>(bp, out);
}

// round 12
// speedup vs baseline: 3.5115x; 1.1815x over previous
#include <cuda_runtime.h>
#include <cuda_fp16.h>
#include <cstdint>

// Problem constants
#define BB 128
#define TT 256
#define CC 384
#define HH 6
#define HS 64
#define MM (BB*TT)       // 32768 rows
#define NW 24576         // 64*384, one head's transposed weight
#define WP_OFF (18*NW)   // offset of Wp^T inside g_wt arrays

// ---------------------------------------------------------------------------
// Scratch (device globals; no allocations allowed)
// ---------------------------------------------------------------------------
__device__ __half g_xh[(size_t)MM*CC];                // x, fp16 (hi only)
__device__ __half g_wth[WP_OFF + CC*CC];              // weights^T hi
__device__ __half g_wtl[WP_OFF + CC*CC];              // weights^T lo
__device__ __half g_qh[(size_t)BB*HH*TT*HS];          // [bh][t][d]
__device__ __half g_ql[(size_t)BB*HH*TT*HS];
__device__ __half g_kh[(size_t)BB*HH*TT*HS];
__device__ __half g_kl[(size_t)BB*HH*TT*HS];
__device__ __half g_vh[(size_t)BB*HH*TT*HS];          // [bh][t][d]  (hi only)
__device__ __half g_oh[(size_t)MM*CC];                // attention out (fp16)

// ---------------------------------------------------------------------------
// Helpers
// ---------------------------------------------------------------------------
__device__ __forceinline__ uint32_t smem_u32(const void* p) {
    uint32_t a;
    asm("{ .reg .u64 t; cvta.to.shared.u64 t, %1; cvt.u32.u64 %0, t; }"
        : "=r"(a) : "l"(p));
    return a;
}

__device__ __forceinline__ void ldm_x4(uint32_t* r, uint32_t addr) {
    asm volatile("ldmatrix.sync.aligned.m8n8.x4.shared.b16 {%0,%1,%2,%3}, [%4];"
                 : "=r"(r[0]), "=r"(r[1]), "=r"(r[2]), "=r"(r[3]) : "r"(addr));
}
__device__ __forceinline__ void ldm_x4t(uint32_t* r, uint32_t addr) {
    asm volatile("ldmatrix.sync.aligned.m8n8.x4.trans.shared.b16 {%0,%1,%2,%3}, [%4];"
                 : "=r"(r[0]), "=r"(r[1]), "=r"(r[2]), "=r"(r[3]) : "r"(addr));
}

__device__ __forceinline__ void mma16816(float* c, const uint32_t* a, const uint32_t* b) {
    asm volatile(
        "mma.sync.aligned.m16n8k16.row.col.f32.f16.f16.f32 "
        "{%0,%1,%2,%3}, {%4,%5,%6,%7}, {%8,%9}, {%0,%1,%2,%3};"
        : "+f"(c[0]), "+f"(c[1]), "+f"(c[2]), "+f"(c[3])
        : "r"(a[0]), "r"(a[1]), "r"(a[2]), "r"(a[3]), "r"(b[0]), "r"(b[1]));
}

__device__ __forceinline__ float ex2f(float x) {
    float y; asm("ex2.approx.ftz.f32 %0, %1;" : "=f"(y) : "f"(x)); return y;
}

__device__ __forceinline__ void hsplit(float v, __half& hi, __half& lo) {
    hi = __float2half_rn(v);
    lo = __float2half_rn(v - __half2float(hi));
}
__device__ __forceinline__ uint32_t pack2(__half a, __half b) {
    __half2 t = __halves2half2(a, b);
    return *reinterpret_cast<uint32_t*>(&t);
}

__device__ __forceinline__ void cpasync16(uint32_t d, const void* s) {
    asm volatile("cp.async.cg.shared.global [%0], [%1], 16;" :: "r"(d), "l"(s));
}
#define CP_COMMIT() asm volatile("cp.async.commit_group;" ::: "memory")
#define CP_WAIT0()  asm volatile("cp.async.wait_group 0;" ::: "memory")

// ---------------------------------------------------------------------------
// Kernel A: convert x -> fp16
// ---------------------------------------------------------------------------
__global__ __launch_bounds__(256) void cvt_x_kernel(const float* __restrict__ x)
{
    int i = blockIdx.x * 256 + threadIdx.x;      // float4 index
    float4 v = ((const float4*)x)[i];
    uint2 u;
    u.x = pack2(__float2half_rn(v.x), __float2half_rn(v.y));
    u.y = pack2(__float2half_rn(v.z), __float2half_rn(v.w));
    ((uint2*)g_xh)[i] = u;
}

// ---------------------------------------------------------------------------
// Kernel B: convert + transpose weights -> fp16 hi/lo
// ---------------------------------------------------------------------------
__global__ __launch_bounds__(256) void cvt_w_kernel(
    const float* __restrict__ Wq, const float* __restrict__ Wk,
    const float* __restrict__ Wv, const float* __restrict__ Wp)
{
    int gi = blockIdx.x * 256 + threadIdx.x;
    float v; size_t dst;
    if (gi < 18 * NW) {
        int g = gi / NW, rem = gi % NW;
        int k = rem / HS, n = rem % HS;
        int mat = g / HH, h = g % HH;
        const float* W = (mat == 0 ? Wq : (mat == 1 ? Wk : Wv));
        v = W[(size_t)h * CC * HS + (size_t)k * HS + n];
        dst = (size_t)g * NW + (size_t)n * CC + k;
    } else {
        int j = gi - 18 * NW;
        int k = j / CC, n = j % CC;
        v = Wp[(size_t)k * CC + n];
        dst = WP_OFF + (size_t)n * CC + k;
    }
    __half hi, lo;
    hsplit(v, hi, lo);
    g_wth[dst] = hi;
    g_wtl[dst] = lo;
}

// ---------------------------------------------------------------------------
// Kernel C: HMMA GEMM, 128x128 tile, BK=64, 2-stage cp.async, 2-pass:
//   D = Ah * (Wh + Wl)^T   (A is fp16; W split hi/lo)
// MODE 0: QKV (grid 256x9; warp n-range = one (mat,head); Q/K split out, V hi)
// MODE 1: proj -> d_out fp32 + bias
// __launch_bounds__(256,2): 2 CTAs/SM (smem 110.6KB x2 = 221KB <= 228KB/SM).
// ---------------------------------------------------------------------------
#define GSTR 144
#define GBUF 18432            // 128 rows * 144B, one tile buffer
#define GEMM_SMEM (6*GBUF)    // A,Bh,Bl x 2 stages

template <int MODE>
__global__ __launch_bounds__(256, 2) void gemm_kernel(
    const float* __restrict__ bp, float* __restrict__ out)
{
    extern __shared__ char smg[];
    const int tid = threadIdx.x;
    const int wid = tid >> 5, lane = tid & 31;
    const int wm = wid & 3, wn = wid >> 2;
    const int m0 = blockIdx.x * 128, n0 = blockIdx.y * 128;

    const __half *Ah, *Bh, *Bl;
    if (MODE == 0) {
        Ah = g_xh;
        Bh = g_wth + (size_t)n0 * CC;
        Bl = g_wtl + (size_t)n0 * CC;
    } else {
        Ah = g_oh;
        Bh = g_wth + WP_OFF + (size_t)n0 * CC;
        Bl = g_wtl + WP_OFF + (size_t)n0 * CC;
    }

    const uint32_t base = smem_u32(smg);
    const uint32_t AH = base, BH = base + 2 * GBUF, BL = base + 4 * GBUF;

    auto prefetch = [&](int st, int c) {
        const int k0 = c * 64;
        #pragma unroll
        for (int i = 0; i < 4; i++) {
            int idx = i * 256 + tid;
            int row = idx >> 3, cj = idx & 7;
            uint32_t so = (uint32_t)(st * GBUF + row * GSTR + cj * 16);
            cpasync16(AH + so, Ah + (size_t)(m0 + row) * CC + k0 + cj * 8);
            cpasync16(BH + so, Bh + (size_t)row * CC + k0 + cj * 8);
            cpasync16(BL + so, Bl + (size_t)row * CC + k0 + cj * 8);
        }
    };

    const int qq = lane >> 3, rr = lane & 7;
    const uint32_t aoff = (uint32_t)((wm * 32 + (qq & 1) * 8 + rr) * GSTR + (qq >> 1) * 16);
    const uint32_t boff = (uint32_t)((wn * 64 + (qq >> 1) * 8 + rr) * GSTR + (qq & 1) * 16);

    float c[2][8][4];
    #pragma unroll
    for (int i = 0; i < 2; i++)
        #pragma unroll
        for (int j = 0; j < 8; j++)
            #pragma unroll
            for (int k = 0; k < 4; k++) c[i][j][k] = 0.f;

    prefetch(0, 0);
    CP_COMMIT();

    #pragma unroll 1
    for (int ch = 0; ch < 6; ch++) {
        CP_WAIT0();
        __syncthreads();
        if (ch < 5) { prefetch((ch + 1) & 1, ch + 1); CP_COMMIT(); }

        const uint32_t st = (uint32_t)((ch & 1) * GBUF);
        #pragma unroll
        for (int ks = 0; ks < 4; ks++) {
            const uint32_t kb = ks * 32;
            uint32_t a_h[2][4], b_h[4][4], b_l[4][4];
            #pragma unroll
            for (int mi = 0; mi < 2; mi++)
                ldm_x4(a_h[mi], AH + st + aoff + mi * (16 * GSTR) + kb);
            #pragma unroll
            for (int nt = 0; nt < 4; nt++) {
                ldm_x4(b_h[nt], BH + st + boff + nt * (16 * GSTR) + kb);
                ldm_x4(b_l[nt], BL + st + boff + nt * (16 * GSTR) + kb);
            }
            #pragma unroll
            for (int mi = 0; mi < 2; mi++)
                #pragma unroll
                for (int ni = 0; ni < 8; ni++)
                    mma16816(c[mi][ni], a_h[mi], &b_h[ni >> 1][(ni & 1) * 2]);
            #pragma unroll
            for (int mi = 0; mi < 2; mi++)
                #pragma unroll
                for (int ni = 0; ni < 8; ni++)
                    mma16816(c[mi][ni], a_h[mi], &b_l[ni >> 1][(ni & 1) * 2]);
        }
    }

    // ---- epilogue ----
    const int gr = lane >> 2, gc = (lane & 3) * 2;
    if (MODE == 0) {
        // warp covers cols [wn*64, wn*64+64) of tile -> exactly one (mat,head)
        int g = blockIdx.y * 2 + wn;          // 0..17
        int mat = g / HH, h = g % HH;
        __half *H, *L = nullptr;
        if (mat == 0)      { H = g_qh; L = g_ql; }
        else if (mat == 1) { H = g_kh; L = g_kl; }
        else               { H = g_vh; }
        #pragma unroll
        for (int mi = 0; mi < 2; mi++) {
            #pragma unroll
            for (int hc = 0; hc < 2; hc++) {
                int m = m0 + wm * 32 + mi * 16 + hc * 8 + gr;
                int b = m >> 8, t = m & (TT - 1);
                size_t rowb = ((size_t)(b * HH + h) * TT + t) * HS;
                #pragma unroll
                for (int ni = 0; ni < 8; ni++) {
                    int d = ni * 8 + gc;
                    __half h0, h1, l0, l1;
                    hsplit(c[mi][ni][hc * 2],     h0, l0);
                    hsplit(c[mi][ni][hc * 2 + 1], h1, l1);
                    *(uint32_t*)(H + rowb + d) = pack2(h0, h1);
                    if (mat < 2)
                        *(uint32_t*)(L + rowb + d) = pack2(l0, l1);
                }
            }
        }
    } else {
        #pragma unroll
        for (int mi = 0; mi < 2; mi++) {
            #pragma unroll
            for (int hc = 0; hc < 2; hc++) {
                int m = m0 + wm * 32 + mi * 16 + hc * 8 + gr;
                float* O = out + (size_t)m * CC + n0;
                #pragma unroll
                for (int ni = 0; ni < 8; ni++) {
                    int col = wn * 64 + ni * 8 + gc;
                    float2 bb = *(const float2*)(bp + n0 + col);
                    float2 v = make_float2(c[mi][ni][hc * 2] + bb.x,
                                           c[mi][ni][hc * 2 + 1] + bb.y);
                    *(float2*)(O + col) = v;
                }
            }
        }
    }
}

// ---------------------------------------------------------------------------
// Kernel D: HMMA flash attention (fp16).
// Block = 128 q-rows of one (b,h). 8 warps x 16 rows. K/V smem-resident.
// S  = qh*kh + qh*kl + ql*kh  (3-pass, full split through softmax)
// PV = ph*vh + pl*vh          (P split, V hi-only)
// V stored [t][d]; PV B-fragments via ldmatrix.x4.trans.
// Output -> g_oh plain fp16.
// ---------------------------------------------------------------------------
#define QSTR 144
#define SQH 0
#define SQL 18432
#define SKH 36864
#define SKL 73728
#define SVH 110592
#define ATTN_SMEM 147456

__global__ __launch_bounds__(256) void attn_hmma_kernel()
{
    extern __shared__ char sm[];
    const int tid = threadIdx.x;
    const int wid = tid >> 5, lane = tid & 31;
    const int bh = blockIdx.y;
    const int b = bh / HH, h = bh % HH;
    const int q0 = (int)blockIdx.x << 7;
    const int kmax = q0 + 128;

    // ---- cooperative loads ----
    {
        const uint4* gqh = (const uint4*)(g_qh + ((size_t)bh * TT + q0) * HS);
        const uint4* gql = (const uint4*)(g_ql + ((size_t)bh * TT + q0) * HS);
        #pragma unroll
        for (int i = 0; i < 4; i++) {
            int idx = tid + i * 256;
            int row = idx >> 3, cj = idx & 7;
            *(uint4*)(sm + SQH + row * QSTR + cj * 16) = gqh[idx];
            *(uint4*)(sm + SQL + row * QSTR + cj * 16) = gql[idx];
        }
        const uint4* gkh = (const uint4*)(g_kh + (size_t)bh * TT * HS);
        const uint4* gkl = (const uint4*)(g_kl + (size_t)bh * TT * HS);
        const uint4* gvh = (const uint4*)(g_vh + (size_t)bh * TT * HS);
        for (int idx = tid; idx < kmax * 8; idx += 256) {
            int row = idx >> 3, cj = idx & 7;
            *(uint4*)(sm + SKH + row * QSTR + cj * 16) = gkh[idx];
            *(uint4*)(sm + SKL + row * QSTR + cj * 16) = gkl[idx];
            *(uint4*)(sm + SVH + row * QSTR + cj * 16) = gvh[idx];
        }
    }
    __syncthreads();

    const int qq = lane >> 3, rr = lane & 7;
    const uint32_t qhB = smem_u32(sm + SQH), qlB = smem_u32(sm + SQL);
    const uint32_t khB = smem_u32(sm + SKH), klB = smem_u32(sm + SKL);
    const uint32_t vhB = smem_u32(sm + SVH);
    const uint32_t aoff = (uint32_t)((wid * 16 + (qq & 1) * 8 + rr) * QSTR + (qq >> 1) * 16);
    const uint32_t krow = (uint32_t)((qq >> 1) * 8 + rr);     // B non-trans (K)
    const uint32_t kcol = (uint32_t)((qq & 1) * 16);
    const uint32_t vrow = (uint32_t)((qq & 1) * 8 + rr);      // B trans (V)
    const uint32_t vcol = (uint32_t)((qq >> 1) * 16);         // bytes (8 halves)

    // Q fragments resident
    uint32_t qh[4][4], ql[4][4];
    #pragma unroll
    for (int ks = 0; ks < 4; ks++) {
        ldm_x4(qh[ks], qhB + aoff + ks * 32);
        ldm_x4(ql[ks], qlB + aoff + ks * 32);
    }

    float o[8][4];
    #pragma unroll
    for (int i = 0; i < 8; i++)
        #pragma unroll
        for (int j = 0; j < 4; j++) o[i][j] = 0.f;

    float m0 = -1e30f, m1 = -1e30f, l0 = 0.f, l1 = 0.f;
    const int gr = lane >> 2, gc = (lane & 3) * 2;
    const int row0 = q0 + wid * 16 + gr;
    const int rmaxw = q0 + wid * 16 + 15;   // warp-uniform
    const float scl = 0.125f * 1.44269504088896f;   // fold log2e into scale

    for (int cb = 0; cb <= rmaxw; cb += 64) {
        float s[8][4];
        #pragma unroll
        for (int i = 0; i < 8; i++)
            #pragma unroll
            for (int j = 0; j < 4; j++) s[i][j] = 0.f;

        // ---- S = Q @ K^T (3-pass) ----
        #pragma unroll
        for (int ks = 0; ks < 4; ks++) {
            uint32_t kh[4][4], kl[4][4];
            #pragma unroll
            for (int nt = 0; nt < 4; nt++) {
                uint32_t ro = (uint32_t)(cb + nt * 16 + krow) * QSTR + kcol + ks * 32;
                ldm_x4(kh[nt], khB + ro);
                ldm_x4(kl[nt], klB + ro);
            }
            #pragma unroll
            for (int ni = 0; ni < 8; ni++)
                mma16816(s[ni], qh[ks], &kh[ni >> 1][(ni & 1) * 2]);
            #pragma unroll
            for (int ni = 0; ni < 8; ni++)
                mma16816(s[ni], qh[ks], &kl[ni >> 1][(ni & 1) * 2]);
            #pragma unroll
            for (int ni = 0; ni < 8; ni++)
                mma16816(s[ni], ql[ks], &kh[ni >> 1][(ni & 1) * 2]);
        }

        // ---- scale + causal mask ----
        #pragma unroll
        for (int ni = 0; ni < 8; ni++) {
            int col = cb + ni * 8 + gc;
            s[ni][0] = (col     <= row0)     ? s[ni][0] * scl : -1e30f;
            s[ni][1] = (col + 1 <= row0)     ? s[ni][1] * scl : -1e30f;
            s[ni][2] = (col     <= row0 + 8) ? s[ni][2] * scl : -1e30f;
            s[ni][3] = (col + 1 <= row0 + 8) ? s[ni][3] * scl : -1e30f;
        }

        // ---- online softmax (base-2) ----
        float a0 = -1e30f, a1 = -1e30f;
        #pragma unroll
        for (int ni = 0; ni < 8; ni++) {
            a0 = fmaxf(a0, fmaxf(s[ni][0], s[ni][1]));
            a1 = fmaxf(a1, fmaxf(s[ni][2], s[ni][3]));
        }
        a0 = fmaxf(a0, __shfl_xor_sync(0xffffffffu, a0, 1));
        a0 = fmaxf(a0, __shfl_xor_sync(0xffffffffu, a0, 2));
        a1 = fmaxf(a1, __shfl_xor_sync(0xffffffffu, a1, 1));
        a1 = fmaxf(a1, __shfl_xor_sync(0xffffffffu, a1, 2));
        float mn0 = fmaxf(m0, a0), mn1 = fmaxf(m1, a1);
        float c0 = ex2f(m0 - mn0), c1 = ex2f(m1 - mn1);
        float ls0 = 0.f, ls1 = 0.f;
        #pragma unroll
        for (int ni = 0; ni < 8; ni++) {
            s[ni][0] = ex2f(s[ni][0] - mn0); ls0 += s[ni][0];
            s[ni][1] = ex2f(s[ni][1] - mn0); ls0 += s[ni][1];
            s[ni][2] = ex2f(s[ni][2] - mn1); ls1 += s[ni][2];
            s[ni][3] = ex2f(s[ni][3] - mn1); ls1 += s[ni][3];
        }
        l0 = l0 * c0 + ls0;
        l1 = l1 * c1 + ls1;
        m0 = mn0; m1 = mn1;
        #pragma unroll
        for (int ni = 0; ni < 8; ni++) {
            o[ni][0] *= c0; o[ni][1] *= c0;
            o[ni][2] *= c1; o[ni][3] *= c1;
        }

        // ---- O += P @ V (P split, V hi; B-frags via ldmatrix.trans) ----
        #pragma unroll
        for (int g = 0; g < 4; g++) {
            uint32_t ph[4], pl[4];
            {
                __half x0, x1, y0, y1;
                hsplit(s[2*g][0], x0, y0); hsplit(s[2*g][1], x1, y1);
                ph[0] = pack2(x0, x1); pl[0] = pack2(y0, y1);
                hsplit(s[2*g][2], x0, y0); hsplit(s[2*g][3], x1, y1);
                ph[1] = pack2(x0, x1); pl[1] = pack2(y0, y1);
                hsplit(s[2*g+1][0], x0, y0); hsplit(s[2*g+1][1], x1, y1);
                ph[2] = pack2(x0, x1); pl[2] = pack2(y0, y1);
                hsplit(s[2*g+1][2], x0, y0); hsplit(s[2*g+1][3], x1, y1);
                ph[3] = pack2(x0, x1); pl[3] = pack2(y0, y1);
            }
            #pragma unroll
            for (int nt = 0; nt < 4; nt++) {
                uint32_t ro = (uint32_t)(cb + g * 16 + vrow) * QSTR + nt * 32 + vcol;
                uint32_t vh[4];
                ldm_x4t(vh, vhB + ro);
                mma16816(o[nt * 2],     ph, &vh[0]);
                mma16816(o[nt * 2 + 1], ph, &vh[2]);
                mma16816(o[nt * 2],     pl, &vh[0]);
                mma16816(o[nt * 2 + 1], pl, &vh[2]);
            }
        }
    }

    // ---- finalize (plain fp16 out) ----
    l0 += __shfl_xor_sync(0xffffffffu, l0, 1);
    l0 += __shfl_xor_sync(0xffffffffu, l0, 2);
    l1 += __shfl_xor_sync(0xffffffffu, l1, 1);
    l1 += __shfl_xor_sync(0xffffffffu, l1, 2);
    float i0 = 1.f / l0, i1 = 1.f / l1;

    size_t base0 = ((size_t)b * TT + row0) * CC + h * HS;
    size_t base1 = ((size_t)b * TT + row0 + 8) * CC + h * HS;
    #pragma unroll
    for (int ni = 0; ni < 8; ni++) {
        int d = ni * 8 + gc;
        *(uint32_t*)(g_oh + base0 + d) =
            pack2(__float2half_rn(o[ni][0] * i0), __float2half_rn(o[ni][1] * i0));
        *(uint32_t*)(g_oh + base1 + d) =
            pack2(__float2half_rn(o[ni][2] * i1), __float2half_rn(o[ni][3] * i1));
    }
}

// ---------------------------------------------------------------------------
extern "C" void kernel_launch(void* const* d_in, const int* in_sizes, int n_in,
                              void* d_out, int out_size)
{
    const float* x  = (const float*)d_in[0];
    const float* Wq = (const float*)d_in[1];
    const float* Wk = (const float*)d_in[2];
    const float* Wv = (const float*)d_in[3];
    const float* Wp = (const float*)d_in[4];
    const float* bp = (const float*)d_in[5];
    float* out = (float*)d_out;

    cudaFuncSetAttribute(gemm_kernel<0>,
                         cudaFuncAttributeMaxDynamicSharedMemorySize, GEMM_SMEM);
    cudaFuncSetAttribute(gemm_kernel<1>,
                         cudaFuncAttributeMaxDynamicSharedMemorySize, GEMM_SMEM);
    cudaFuncSetAttribute(attn_hmma_kernel,
                         cudaFuncAttributeMaxDynamicSharedMemorySize, ATTN_SMEM);

    cvt_x_kernel<<<(MM * CC / 4) / 256, 256>>>(x);
    cvt_w_kernel<<<(18 * NW + CC * CC) / 256, 256>>>(Wq, Wk, Wv, Wp);
    gemm_kernel<0><<<dim3(MM / 128, 9), 256, GEMM_SMEM>>>(nullptr, nullptr);
    attn_hmma_kernel<<<dim3(2, BB * HH), 256, ATTN_SMEM>>>();
    gemm_kernel<1><<<dim3(MM / 128, CC / 128), 256, GEMM_SMEM>>>(bp, out);
}

// round 15
// speedup vs baseline: 5.3165x; 1.5140x over previous
#include <cuda_runtime.h>
#include <cuda_fp16.h>
#include <cstdint>

// Problem constants
#define BB 128
#define TT 256
#define CC 384
#define HH 6
#define HS 64
#define MM (BB*TT)       // 32768 rows
#define NW 24576         // 64*384, one head's transposed weight
#define WP_OFF (18*NW)   // offset of Wp^T inside g_wt arrays

// ---------------------------------------------------------------------------
// Scratch (device globals; no allocations allowed)
// ---------------------------------------------------------------------------
__device__ __half g_xh[(size_t)MM*CC];                // x, fp16
__device__ __half g_wth[WP_OFF + CC*CC];              // weights^T hi
__device__ __half g_wtl[WP_OFF + CC*CC];              // weights^T lo (Wp only used)
__device__ __half g_qh[(size_t)BB*HH*TT*HS];          // [bh][t][d] fp16
__device__ __half g_kh[(size_t)BB*HH*TT*HS];
__device__ __half g_vh[(size_t)BB*HH*TT*HS];
__device__ __half g_oh[(size_t)MM*CC];                // attention out (fp16)

// ---------------------------------------------------------------------------
// Helpers
// ---------------------------------------------------------------------------
__device__ __forceinline__ uint32_t smem_u32(const void* p) {
    uint32_t a;
    asm("{ .reg .u64 t; cvta.to.shared.u64 t, %1; cvt.u32.u64 %0, t; }"
        : "=r"(a) : "l"(p));
    return a;
}

__device__ __forceinline__ void ldm_x4(uint32_t* r, uint32_t addr) {
    asm volatile("ldmatrix.sync.aligned.m8n8.x4.shared.b16 {%0,%1,%2,%3}, [%4];"
                 : "=r"(r[0]), "=r"(r[1]), "=r"(r[2]), "=r"(r[3]) : "r"(addr));
}
__device__ __forceinline__ void ldm_x4t(uint32_t* r, uint32_t addr) {
    asm volatile("ldmatrix.sync.aligned.m8n8.x4.trans.shared.b16 {%0,%1,%2,%3}, [%4];"
                 : "=r"(r[0]), "=r"(r[1]), "=r"(r[2]), "=r"(r[3]) : "r"(addr));
}

__device__ __forceinline__ void mma16816(float* c, const uint32_t* a, const uint32_t* b) {
    asm volatile(
        "mma.sync.aligned.m16n8k16.row.col.f32.f16.f16.f32 "
        "{%0,%1,%2,%3}, {%4,%5,%6,%7}, {%8,%9}, {%0,%1,%2,%3};"
        : "+f"(c[0]), "+f"(c[1]), "+f"(c[2]), "+f"(c[3])
        : "r"(a[0]), "r"(a[1]), "r"(a[2]), "r"(a[3]), "r"(b[0]), "r"(b[1]));
}

__device__ __forceinline__ float ex2f(float x) {
    float y; asm("ex2.approx.ftz.f32 %0, %1;" : "=f"(y) : "f"(x)); return y;
}

__device__ __forceinline__ void hsplit(float v, __half& hi, __half& lo) {
    hi = __float2half_rn(v);
    lo = __float2half_rn(v - __half2float(hi));
}
__device__ __forceinline__ uint32_t pack2(__half a, __half b) {
    __half2 t = __halves2half2(a, b);
    return *reinterpret_cast<uint32_t*>(&t);
}

__device__ __forceinline__ void cpasync16(uint32_t d, const void* s) {
    asm volatile("cp.async.cg.shared.global [%0], [%1], 16;" :: "r"(d), "l"(s));
}
#define CP_COMMIT() asm volatile("cp.async.commit_group;" ::: "memory")
#define CP_WAIT0()  asm volatile("cp.async.wait_group 0;" ::: "memory")

// ---------------------------------------------------------------------------
// Kernel A: convert x -> fp16
// ---------------------------------------------------------------------------
__global__ __launch_bounds__(256) void cvt_x_kernel(const float* __restrict__ x)
{
    int i = blockIdx.x * 256 + threadIdx.x;      // float4 index
    float4 v = ((const float4*)x)[i];
    uint2 u;
    u.x = pack2(__float2half_rn(v.x), __float2half_rn(v.y));
    u.y = pack2(__float2half_rn(v.z), __float2half_rn(v.w));
    ((uint2*)g_xh)[i] = u;
}

// ---------------------------------------------------------------------------
// Kernel B: convert + transpose weights -> fp16 hi/lo
// ---------------------------------------------------------------------------
__global__ __launch_bounds__(256) void cvt_w_kernel(
    const float* __restrict__ Wq, const float* __restrict__ Wk,
    const float* __restrict__ Wv, const float* __restrict__ Wp)
{
    int gi = blockIdx.x * 256 + threadIdx.x;
    float v; size_t dst;
    if (gi < 18 * NW) {
        int g = gi / NW, rem = gi % NW;
        int k = rem / HS, n = rem % HS;
        int mat = g / HH, h = g % HH;
        const float* W = (mat == 0 ? Wq : (mat == 1 ? Wk : Wv));
        v = W[(size_t)h * CC * HS + (size_t)k * HS + n];
        dst = (size_t)g * NW + (size_t)n * CC + k;
    } else {
        int j = gi - 18 * NW;
        int k = j / CC, n = j % CC;
        v = Wp[(size_t)k * CC + n];
        dst = WP_OFF + (size_t)n * CC + k;
    }
    __half hi, lo;
    hsplit(v, hi, lo);
    g_wth[dst] = hi;
    g_wtl[dst] = lo;
}

// ---------------------------------------------------------------------------
// Kernel C: HMMA GEMM, 128x128 tile, BK=64, 2-stage cp.async.
// MODE 0, PASSES 1: QKV.  D = xh * Wh^T.  (score precision is free; V picks up
//   ~2e-4 from W-quant which fits the budget)  -> q/k/v plain fp16 [bh][t][d]
// MODE 1, PASSES 2: proj. D = O * (Wh+Wl)^T + bias -> d_out fp32
// __launch_bounds__(256,2): 2 CTAs/SM.
// ---------------------------------------------------------------------------
#define GSTR 144
#define GBUF 18432            // 128 rows * 144B, one tile buffer

template <int MODE, int PASSES>
__global__ __launch_bounds__(256, 2) void gemm_kernel(
    const float* __restrict__ bp, float* __restrict__ out)
{
    extern __shared__ char smg[];
    const int tid = threadIdx.x;
    const int wid = tid >> 5, lane = tid & 31;
    const int wm = wid & 3, wn = wid >> 2;
    const int m0 = blockIdx.x * 128, n0 = blockIdx.y * 128;

    const __half *Ah, *Bh, *Bl = nullptr;
    if (MODE == 0) {
        Ah = g_xh;
        Bh = g_wth + (size_t)n0 * CC;
    } else {
        Ah = g_oh;
        Bh = g_wth + WP_OFF + (size_t)n0 * CC;
        Bl = g_wtl + WP_OFF + (size_t)n0 * CC;
    }

    const uint32_t base = smem_u32(smg);
    const uint32_t AH = base, BH = base + 2 * GBUF, BL = base + 4 * GBUF;

    auto prefetch = [&](int st, int c) {
        const int k0 = c * 64;
        #pragma unroll
        for (int i = 0; i < 4; i++) {
            int idx = i * 256 + tid;
            int row = idx >> 3, cj = idx & 7;
            uint32_t so = (uint32_t)(st * GBUF + row * GSTR + cj * 16);
            cpasync16(AH + so, Ah + (size_t)(m0 + row) * CC + k0 + cj * 8);
            cpasync16(BH + so, Bh + (size_t)row * CC + k0 + cj * 8);
            if (PASSES == 2)
                cpasync16(BL + so, Bl + (size_t)row * CC + k0 + cj * 8);
        }
    };

    const int qq = lane >> 3, rr = lane & 7;
    const uint32_t aoff = (uint32_t)((wm * 32 + (qq & 1) * 8 + rr) * GSTR + (qq >> 1) * 16);
    const uint32_t boff = (uint32_t)((wn * 64 + (qq >> 1) * 8 + rr) * GSTR + (qq & 1) * 16);

    float c[2][8][4];
    #pragma unroll
    for (int i = 0; i < 2; i++)
        #pragma unroll
        for (int j = 0; j < 8; j++)
            #pragma unroll
            for (int k = 0; k < 4; k++) c[i][j][k] = 0.f;

    prefetch(0, 0);
    CP_COMMIT();

    #pragma unroll 1
    for (int ch = 0; ch < 6; ch++) {
        CP_WAIT0();
        __syncthreads();
        if (ch < 5) { prefetch((ch + 1) & 1, ch + 1); CP_COMMIT(); }

        const uint32_t st = (uint32_t)((ch & 1) * GBUF);
        #pragma unroll
        for (int ks = 0; ks < 4; ks++) {
            const uint32_t kb = ks * 32;
            uint32_t a_h[2][4], b_h[4][4], b_l[4][4];
            #pragma unroll
            for (int mi = 0; mi < 2; mi++)
                ldm_x4(a_h[mi], AH + st + aoff + mi * (16 * GSTR) + kb);
            #pragma unroll
            for (int nt = 0; nt < 4; nt++) {
                ldm_x4(b_h[nt], BH + st + boff + nt * (16 * GSTR) + kb);
                if (PASSES == 2)
                    ldm_x4(b_l[nt], BL + st + boff + nt * (16 * GSTR) + kb);
            }
            #pragma unroll
            for (int mi = 0; mi < 2; mi++)
                #pragma unroll
                for (int ni = 0; ni < 8; ni++)
                    mma16816(c[mi][ni], a_h[mi], &b_h[ni >> 1][(ni & 1) * 2]);
            if (PASSES == 2) {
                #pragma unroll
                for (int mi = 0; mi < 2; mi++)
                    #pragma unroll
                    for (int ni = 0; ni < 8; ni++)
                        mma16816(c[mi][ni], a_h[mi], &b_l[ni >> 1][(ni & 1) * 2]);
            }
        }
    }

    // ---- epilogue ----
    const int gr = lane >> 2, gc = (lane & 3) * 2;
    if (MODE == 0) {
        // warp covers cols [wn*64, wn*64+64) -> exactly one (mat,head)
        int g = blockIdx.y * 2 + wn;          // 0..17
        int mat = g / HH, h = g % HH;
        __half* H = (mat == 0) ? g_qh : (mat == 1) ? g_kh : g_vh;
        #pragma unroll
        for (int mi = 0; mi < 2; mi++) {
            #pragma unroll
            for (int hc = 0; hc < 2; hc++) {
                int m = m0 + wm * 32 + mi * 16 + hc * 8 + gr;
                int b = m >> 8, t = m & (TT - 1);
                size_t rowb = ((size_t)(b * HH + h) * TT + t) * HS;
                #pragma unroll
                for (int ni = 0; ni < 8; ni++) {
                    int d = ni * 8 + gc;
                    *(uint32_t*)(H + rowb + d) =
                        pack2(__float2half_rn(c[mi][ni][hc * 2]),
                              __float2half_rn(c[mi][ni][hc * 2 + 1]));
                }
            }
        }
    } else {
        #pragma unroll
        for (int mi = 0; mi < 2; mi++) {
            #pragma unroll
            for (int hc = 0; hc < 2; hc++) {
                int m = m0 + wm * 32 + mi * 16 + hc * 8 + gr;
                float* O = out + (size_t)m * CC + n0;
                #pragma unroll
                for (int ni = 0; ni < 8; ni++) {
                    int col = wn * 64 + ni * 8 + gc;
                    float2 bb = *(const float2*)(bp + n0 + col);
                    float2 v = make_float2(c[mi][ni][hc * 2] + bb.x,
                                           c[mi][ni][hc * 2 + 1] + bb.y);
                    *(float2*)(O + col) = v;
                }
            }
        }
    }
}

// ---------------------------------------------------------------------------
// Kernel D: HMMA flash attention (fp16, lean).
// Block = 128 q-rows of one (b,h). 8 warps x 16 rows. K/V smem-resident.
// S  = q*k (1-pass; logits ~0.15 sigma -> precision free)
// PV = ph*vh + pl*vh (P split, V fp16)
// smem 92KB -> 2 CTAs/SM.
// ---------------------------------------------------------------------------
#define QSTR 144
#define SQH 0
#define SKH 18432
#define SVH 55296
#define ATTN_SMEM 92160

__global__ __launch_bounds__(256, 2) void attn_hmma_kernel()
{
    extern __shared__ char sm[];
    const int tid = threadIdx.x;
    const int wid = tid >> 5, lane = tid & 31;
    const int bh = blockIdx.y;
    const int b = bh / HH, h = bh % HH;
    const int q0 = (int)blockIdx.x << 7;
    const int kmax = q0 + 128;

    // ---- cooperative loads ----
    {
        const uint4* gqh = (const uint4*)(g_qh + ((size_t)bh * TT + q0) * HS);
        #pragma unroll
        for (int i = 0; i < 4; i++) {
            int idx = tid + i * 256;
            int row = idx >> 3, cj = idx & 7;
            *(uint4*)(sm + SQH + row * QSTR + cj * 16) = gqh[idx];
        }
        const uint4* gkh = (const uint4*)(g_kh + (size_t)bh * TT * HS);
        const uint4* gvh = (const uint4*)(g_vh + (size_t)bh * TT * HS);
        for (int idx = tid; idx < kmax * 8; idx += 256) {
            int row = idx >> 3, cj = idx & 7;
            *(uint4*)(sm + SKH + row * QSTR + cj * 16) = gkh[idx];
            *(uint4*)(sm + SVH + row * QSTR + cj * 16) = gvh[idx];
        }
    }
    __syncthreads();

    const int qq = lane >> 3, rr = lane & 7;
    const uint32_t qhB = smem_u32(sm + SQH);
    const uint32_t khB = smem_u32(sm + SKH);
    const uint32_t vhB = smem_u32(sm + SVH);
    const uint32_t aoff = (uint32_t)((wid * 16 + (qq & 1) * 8 + rr) * QSTR + (qq >> 1) * 16);
    const uint32_t krow = (uint32_t)((qq >> 1) * 8 + rr);     // B non-trans (K)
    const uint32_t kcol = (uint32_t)((qq & 1) * 16);
    const uint32_t vrow = (uint32_t)((qq & 1) * 8 + rr);      // B trans (V)
    const uint32_t vcol = (uint32_t)((qq >> 1) * 16);         // bytes (8 halves)

    // Q fragments resident
    uint32_t qh[4][4];
    #pragma unroll
    for (int ks = 0; ks < 4; ks++)
        ldm_x4(qh[ks], qhB + aoff + ks * 32);

    float o[8][4];
    #pragma unroll
    for (int i = 0; i < 8; i++)
        #pragma unroll
        for (int j = 0; j < 4; j++) o[i][j] = 0.f;

    float m0 = -1e30f, m1 = -1e30f, l0 = 0.f, l1 = 0.f;
    const int gr = lane >> 2, gc = (lane & 3) * 2;
    const int row0 = q0 + wid * 16 + gr;
    const int rmaxw = q0 + wid * 16 + 15;   // warp-uniform
    const float scl = 0.125f * 1.44269504088896f;   // fold log2e into scale

    for (int cb = 0; cb <= rmaxw; cb += 64) {
        float s[8][4];
        #pragma unroll
        for (int i = 0; i < 8; i++)
            #pragma unroll
            for (int j = 0; j < 4; j++) s[i][j] = 0.f;

        // ---- S = Q @ K^T (1-pass fp16) ----
        #pragma unroll
        for (int ks = 0; ks < 4; ks++) {
            uint32_t kh[4][4];
            #pragma unroll
            for (int nt = 0; nt < 4; nt++) {
                uint32_t ro = (uint32_t)(cb + nt * 16 + krow) * QSTR + kcol + ks * 32;
                ldm_x4(kh[nt], khB + ro);
            }
            #pragma unroll
            for (int ni = 0; ni < 8; ni++)
                mma16816(s[ni], qh[ks], &kh[ni >> 1][(ni & 1) * 2]);
        }

        // ---- scale + causal mask ----
        #pragma unroll
        for (int ni = 0; ni < 8; ni++) {
            int col = cb + ni * 8 + gc;
            s[ni][0] = (col     <= row0)     ? s[ni][0] * scl : -1e30f;
            s[ni][1] = (col + 1 <= row0)     ? s[ni][1] * scl : -1e30f;
            s[ni][2] = (col     <= row0 + 8) ? s[ni][2] * scl : -1e30f;
            s[ni][3] = (col + 1 <= row0 + 8) ? s[ni][3] * scl : -1e30f;
        }

        // ---- online softmax (base-2) ----
        float a0 = -1e30f, a1 = -1e30f;
        #pragma unroll
        for (int ni = 0; ni < 8; ni++) {
            a0 = fmaxf(a0, fmaxf(s[ni][0], s[ni][1]));
            a1 = fmaxf(a1, fmaxf(s[ni][2], s[ni][3]));
        }
        a0 = fmaxf(a0, __shfl_xor_sync(0xffffffffu, a0, 1));
        a0 = fmaxf(a0, __shfl_xor_sync(0xffffffffu, a0, 2));
        a1 = fmaxf(a1, __shfl_xor_sync(0xffffffffu, a1, 1));
        a1 = fmaxf(a1, __shfl_xor_sync(0xffffffffu, a1, 2));
        float mn0 = fmaxf(m0, a0), mn1 = fmaxf(m1, a1);
        float c0 = ex2f(m0 - mn0), c1 = ex2f(m1 - mn1);
        float ls0 = 0.f, ls1 = 0.f;
        #pragma unroll
        for (int ni = 0; ni < 8; ni++) {
            s[ni][0] = ex2f(s[ni][0] - mn0); ls0 += s[ni][0];
            s[ni][1] = ex2f(s[ni][1] - mn0); ls0 += s[ni][1];
            s[ni][2] = ex2f(s[ni][2] - mn1); ls1 += s[ni][2];
            s[ni][3] = ex2f(s[ni][3] - mn1); ls1 += s[ni][3];
        }
        l0 = l0 * c0 + ls0;
        l1 = l1 * c1 + ls1;
        m0 = mn0; m1 = mn1;
        #pragma unroll
        for (int ni = 0; ni < 8; ni++) {
            o[ni][0] *= c0; o[ni][1] *= c0;
            o[ni][2] *= c1; o[ni][3] *= c1;
        }

        // ---- O += P @ V (P split, V fp16; B-frags via ldmatrix.trans) ----
        #pragma unroll
        for (int g = 0; g < 4; g++) {
            uint32_t ph[4], pl[4];
            {
                __half x0, x1, y0, y1;
                hsplit(s[2*g][0], x0, y0); hsplit(s[2*g][1], x1, y1);
                ph[0] = pack2(x0, x1); pl[0] = pack2(y0, y1);
                hsplit(s[2*g][2], x0, y0); hsplit(s[2*g][3], x1, y1);
                ph[1] = pack2(x0, x1); pl[1] = pack2(y0, y1);
                hsplit(s[2*g+1][0], x0, y0); hsplit(s[2*g+1][1], x1, y1);
                ph[2] = pack2(x0, x1); pl[2] = pack2(y0, y1);
                hsplit(s[2*g+1][2], x0, y0); hsplit(s[2*g+1][3], x1, y1);
                ph[3] = pack2(x0, x1); pl[3] = pack2(y0, y1);
            }
            #pragma unroll
            for (int nt = 0; nt < 4; nt++) {
                uint32_t ro = (uint32_t)(cb + g * 16 + vrow) * QSTR + nt * 32 + vcol;
                uint32_t vh[4];
                ldm_x4t(vh, vhB + ro);
                mma16816(o[nt * 2],     ph, &vh[0]);
                mma16816(o[nt * 2 + 1], ph, &vh[2]);
                mma16816(o[nt * 2],     pl, &vh[0]);
                mma16816(o[nt * 2 + 1], pl, &vh[2]);
            }
        }
    }

    // ---- finalize (plain fp16 out) ----
    l0 += __shfl_xor_sync(0xffffffffu, l0, 1);
    l0 += __shfl_xor_sync(0xffffffffu, l0, 2);
    l1 += __shfl_xor_sync(0xffffffffu, l1, 1);
    l1 += __shfl_xor_sync(0xffffffffu, l1, 2);
    float i0 = 1.f / l0, i1 = 1.f / l1;

    size_t base0 = ((size_t)b * TT + row0) * CC + h * HS;
    size_t base1 = ((size_t)b * TT + row0 + 8) * CC + h * HS;
    #pragma unroll
    for (int ni = 0; ni < 8; ni++) {
        int d = ni * 8 + gc;
        *(uint32_t*)(g_oh + base0 + d) =
            pack2(__float2half_rn(o[ni][0] * i0), __float2half_rn(o[ni][1] * i0));
        *(uint32_t*)(g_oh + base1 + d) =
            pack2(__float2half_rn(o[ni][2] * i1), __float2half_rn(o[ni][3] * i1));
    }
}

// ---------------------------------------------------------------------------
extern "C" void kernel_launch(void* const* d_in, const int* in_sizes, int n_in,
                              void* d_out, int out_size)
{
    const float* x  = (const float*)d_in[0];
    const float* Wq = (const float*)d_in[1];
    const float* Wk = (const float*)d_in[2];
    const float* Wv = (const float*)d_in[3];
    const float* Wp = (const float*)d_in[4];
    const float* bp = (const float*)d_in[5];
    float* out = (float*)d_out;

    cudaFuncSetAttribute(gemm_kernel<0, 1>,
                         cudaFuncAttributeMaxDynamicSharedMemorySize, 4 * GBUF);
    cudaFuncSetAttribute(gemm_kernel<1, 2>,
                         cudaFuncAttributeMaxDynamicSharedMemorySize, 6 * GBUF);
    cudaFuncSetAttribute(attn_hmma_kernel,
                         cudaFuncAttributeMaxDynamicSharedMemorySize, ATTN_SMEM);

    cvt_x_kernel<<<(MM * CC / 4) / 256, 256>>>(x);
    cvt_w_kernel<<<(18 * NW + CC * CC) / 256, 256>>>(Wq, Wk, Wv, Wp);
    gemm_kernel<0, 1><<<dim3(MM / 128, 9), 256, 4 * GBUF>>>(nullptr, nullptr);
    attn_hmma_kernel<<<dim3(2, BB * HH), 256, ATTN_SMEM>>>();
    gemm_kernel<1, 2><<<dim3(MM / 128, CC / 128), 256, 6 * GBUF>>>(bp, out);
}

// round 16
// speedup vs baseline: 6.4469x; 1.2126x over previous
#include <cuda_runtime.h>
#include <cuda_fp16.h>
#include <cstdint>

// Problem constants
#define BB 128
#define TT 256
#define CC 384
#define HH 6
#define HS 64
#define MM (BB*TT)       // 32768 rows
#define NW 24576         // 64*384, one head's transposed weight
#define WP_OFF (18*NW)   // offset of Wp^T inside g_wth

// softmax scale folded into Q: 1/sqrt(64) * log2(e)
#define SCLF 0.18033688f

// ---------------------------------------------------------------------------
// Scratch (device globals; no allocations allowed)
// ---------------------------------------------------------------------------
__device__ __half g_xh[(size_t)MM*CC];                // x, fp16
__device__ __half g_wth[WP_OFF + CC*CC];              // weights^T (fp16)
__device__ __half g_qh[(size_t)BB*HH*TT*HS];          // [bh][t][d], pre-scaled
__device__ __half g_kh[(size_t)BB*HH*TT*HS];
__device__ __half g_vh[(size_t)BB*HH*TT*HS];
__device__ __half g_oh[(size_t)MM*CC];                // attention out (fp16)

// ---------------------------------------------------------------------------
// Helpers
// ---------------------------------------------------------------------------
__device__ __forceinline__ uint32_t smem_u32(const void* p) {
    uint32_t a;
    asm("{ .reg .u64 t; cvta.to.shared.u64 t, %1; cvt.u32.u64 %0, t; }"
        : "=r"(a) : "l"(p));
    return a;
}

__device__ __forceinline__ void ldm_x4(uint32_t* r, uint32_t addr) {
    asm volatile("ldmatrix.sync.aligned.m8n8.x4.shared.b16 {%0,%1,%2,%3}, [%4];"
                 : "=r"(r[0]), "=r"(r[1]), "=r"(r[2]), "=r"(r[3]) : "r"(addr));
}
__device__ __forceinline__ void ldm_x4t(uint32_t* r, uint32_t addr) {
    asm volatile("ldmatrix.sync.aligned.m8n8.x4.trans.shared.b16 {%0,%1,%2,%3}, [%4];"
                 : "=r"(r[0]), "=r"(r[1]), "=r"(r[2]), "=r"(r[3]) : "r"(addr));
}

__device__ __forceinline__ void mma16816(float* c, const uint32_t* a, const uint32_t* b) {
    asm volatile(
        "mma.sync.aligned.m16n8k16.row.col.f32.f16.f16.f32 "
        "{%0,%1,%2,%3}, {%4,%5,%6,%7}, {%8,%9}, {%0,%1,%2,%3};"
        : "+f"(c[0]), "+f"(c[1]), "+f"(c[2]), "+f"(c[3])
        : "r"(a[0]), "r"(a[1]), "r"(a[2]), "r"(a[3]), "r"(b[0]), "r"(b[1]));
}

__device__ __forceinline__ float ex2f(float x) {
    float y; asm("ex2.approx.ftz.f32 %0, %1;" : "=f"(y) : "f"(x)); return y;
}

__device__ __forceinline__ uint32_t pack2(__half a, __half b) {
    __half2 t = __halves2half2(a, b);
    return *reinterpret_cast<uint32_t*>(&t);
}

__device__ __forceinline__ void cpasync16(uint32_t d, const void* s) {
    asm volatile("cp.async.cg.shared.global [%0], [%1], 16;" :: "r"(d), "l"(s));
}
#define CP_COMMIT() asm volatile("cp.async.commit_group;" ::: "memory")
#define CP_WAIT0()  asm volatile("cp.async.wait_group 0;" ::: "memory")

// ---------------------------------------------------------------------------
// Kernel A: fused converts.  blocks [0,12288): x -> fp16.
//                            blocks [12288,14592): weights^T -> fp16 (hi only).
// ---------------------------------------------------------------------------
#define CVT_XBLK 12288
#define CVT_WBLK 2304

__global__ __launch_bounds__(256) void cvt_kernel(
    const float* __restrict__ x,
    const float* __restrict__ Wq, const float* __restrict__ Wk,
    const float* __restrict__ Wv, const float* __restrict__ Wp)
{
    int bid = blockIdx.x;
    if (bid < CVT_XBLK) {
        int i = bid * 256 + threadIdx.x;      // float4 index
        float4 v = ((const float4*)x)[i];
        uint2 u;
        u.x = pack2(__float2half_rn(v.x), __float2half_rn(v.y));
        u.y = pack2(__float2half_rn(v.z), __float2half_rn(v.w));
        ((uint2*)g_xh)[i] = u;
    } else {
        int gi = (bid - CVT_XBLK) * 256 + threadIdx.x;
        float v; size_t dst;
        if (gi < 18 * NW) {
            int g = gi / NW, rem = gi % NW;
            int k = rem / HS, n = rem % HS;
            int mat = g / HH, h = g % HH;
            const float* W = (mat == 0 ? Wq : (mat == 1 ? Wk : Wv));
            v = W[(size_t)h * CC * HS + (size_t)k * HS + n];
            dst = (size_t)g * NW + (size_t)n * CC + k;
        } else {
            int j = gi - 18 * NW;
            int k = j / CC, n = j % CC;
            v = Wp[(size_t)k * CC + n];
            dst = WP_OFF + (size_t)n * CC + k;
        }
        g_wth[dst] = __float2half_rn(v);
    }
}

// ---------------------------------------------------------------------------
// Kernel C: HMMA GEMM, 128x128 tile, BK=64, 2-stage cp.async, 1-pass fp16.
// MODE 0: QKV  -> q/k/v fp16 [bh][t][d]; Q scaled by SCLF.
// MODE 1: proj -> d_out fp32 + bias.
// __launch_bounds__(256,2): 2 CTAs/SM (smem 73.7KB x2).
// ---------------------------------------------------------------------------
#define GSTR 144
#define GBUF 18432            // 128 rows * 144B
#define GEMM_SMEM (4*GBUF)

template <int MODE>
__global__ __launch_bounds__(256, 2) void gemm_kernel(
    const float* __restrict__ bp, float* __restrict__ out)
{
    extern __shared__ char smg[];
    const int tid = threadIdx.x;
    const int wid = tid >> 5, lane = tid & 31;
    const int wm = wid & 3, wn = wid >> 2;
    const int m0 = blockIdx.x * 128, n0 = blockIdx.y * 128;

    const __half *Ah, *Bh;
    if (MODE == 0) {
        Ah = g_xh;
        Bh = g_wth + (size_t)n0 * CC;
    } else {
        Ah = g_oh;
        Bh = g_wth + WP_OFF + (size_t)n0 * CC;
    }

    const uint32_t base = smem_u32(smg);
    const uint32_t AH = base, BH = base + 2 * GBUF;

    auto prefetch = [&](int st, int c) {
        const int k0 = c * 64;
        #pragma unroll
        for (int i = 0; i < 4; i++) {
            int idx = i * 256 + tid;
            int row = idx >> 3, cj = idx & 7;
            uint32_t so = (uint32_t)(st * GBUF + row * GSTR + cj * 16);
            cpasync16(AH + so, Ah + (size_t)(m0 + row) * CC + k0 + cj * 8);
            cpasync16(BH + so, Bh + (size_t)row * CC + k0 + cj * 8);
        }
    };

    const int qq = lane >> 3, rr = lane & 7;
    const uint32_t aoff = (uint32_t)((wm * 32 + (qq & 1) * 8 + rr) * GSTR + (qq >> 1) * 16);
    const uint32_t boff = (uint32_t)((wn * 64 + (qq >> 1) * 8 + rr) * GSTR + (qq & 1) * 16);

    float c[2][8][4];
    #pragma unroll
    for (int i = 0; i < 2; i++)
        #pragma unroll
        for (int j = 0; j < 8; j++)
            #pragma unroll
            for (int k = 0; k < 4; k++) c[i][j][k] = 0.f;

    prefetch(0, 0);
    CP_COMMIT();

    #pragma unroll 1
    for (int ch = 0; ch < 6; ch++) {
        CP_WAIT0();
        __syncthreads();
        if (ch < 5) { prefetch((ch + 1) & 1, ch + 1); CP_COMMIT(); }

        const uint32_t st = (uint32_t)((ch & 1) * GBUF);
        #pragma unroll
        for (int ks = 0; ks < 4; ks++) {
            const uint32_t kb = ks * 32;
            uint32_t a_h[2][4], b_h[4][4];
            #pragma unroll
            for (int mi = 0; mi < 2; mi++)
                ldm_x4(a_h[mi], AH + st + aoff + mi * (16 * GSTR) + kb);
            #pragma unroll
            for (int nt = 0; nt < 4; nt++)
                ldm_x4(b_h[nt], BH + st + boff + nt * (16 * GSTR) + kb);
            #pragma unroll
            for (int mi = 0; mi < 2; mi++)
                #pragma unroll
                for (int ni = 0; ni < 8; ni++)
                    mma16816(c[mi][ni], a_h[mi], &b_h[ni >> 1][(ni & 1) * 2]);
        }
    }

    // ---- epilogue ----
    const int gr = lane >> 2, gc = (lane & 3) * 2;
    if (MODE == 0) {
        // warp covers cols [wn*64, wn*64+64) -> exactly one (mat,head)
        int g = blockIdx.y * 2 + wn;          // 0..17
        int mat = g / HH, h = g % HH;
        __half* H = (mat == 0) ? g_qh : (mat == 1) ? g_kh : g_vh;
        const float qs = (mat == 0) ? SCLF : 1.f;
        #pragma unroll
        for (int mi = 0; mi < 2; mi++) {
            #pragma unroll
            for (int hc = 0; hc < 2; hc++) {
                int m = m0 + wm * 32 + mi * 16 + hc * 8 + gr;
                int b = m >> 8, t = m & (TT - 1);
                size_t rowb = ((size_t)(b * HH + h) * TT + t) * HS;
                #pragma unroll
                for (int ni = 0; ni < 8; ni++) {
                    int d = ni * 8 + gc;
                    *(uint32_t*)(H + rowb + d) =
                        pack2(__float2half_rn(c[mi][ni][hc * 2] * qs),
                              __float2half_rn(c[mi][ni][hc * 2 + 1] * qs));
                }
            }
        }
    } else {
        #pragma unroll
        for (int mi = 0; mi < 2; mi++) {
            #pragma unroll
            for (int hc = 0; hc < 2; hc++) {
                int m = m0 + wm * 32 + mi * 16 + hc * 8 + gr;
                float* O = out + (size_t)m * CC + n0;
                #pragma unroll
                for (int ni = 0; ni < 8; ni++) {
                    int col = wn * 64 + ni * 8 + gc;
                    float2 bb = *(const float2*)(bp + n0 + col);
                    float2 v = make_float2(c[mi][ni][hc * 2] + bb.x,
                                           c[mi][ni][hc * 2 + 1] + bb.y);
                    *(float2*)(O + col) = v;
                }
            }
        }
    }
}

// ---------------------------------------------------------------------------
// Kernel D: HMMA flash attention (fp16, lean).
// Block = 128 q-rows of one (b,h). 8 warps x 16 rows. K/V smem-resident.
// Q pre-scaled by SCLF -> S arrives in log2 domain, no per-element multiply.
// Per warp: full chunks below the diagonal need NO mask; exactly one diagonal
// chunk gets the causal select. S and PV both 1-pass fp16.
// smem 92KB -> 2 CTAs/SM.
// ---------------------------------------------------------------------------
#define QSTR 144
#define SQH 0
#define SKH 18432
#define SVH 55296
#define ATTN_SMEM 92160

__global__ __launch_bounds__(256, 2) void attn_hmma_kernel()
{
    extern __shared__ char sm[];
    const int tid = threadIdx.x;
    const int wid = tid >> 5, lane = tid & 31;
    const int bh = blockIdx.y;
    const int b = bh / HH, h = bh % HH;
    const int q0 = (int)blockIdx.x << 7;
    const int kmax = q0 + 128;

    // ---- cooperative loads ----
    {
        const uint4* gqh = (const uint4*)(g_qh + ((size_t)bh * TT + q0) * HS);
        #pragma unroll
        for (int i = 0; i < 4; i++) {
            int idx = tid + i * 256;
            int row = idx >> 3, cj = idx & 7;
            *(uint4*)(sm + SQH + row * QSTR + cj * 16) = gqh[idx];
        }
        const uint4* gkh = (const uint4*)(g_kh + (size_t)bh * TT * HS);
        const uint4* gvh = (const uint4*)(g_vh + (size_t)bh * TT * HS);
        for (int idx = tid; idx < kmax * 8; idx += 256) {
            int row = idx >> 3, cj = idx & 7;
            *(uint4*)(sm + SKH + row * QSTR + cj * 16) = gkh[idx];
            *(uint4*)(sm + SVH + row * QSTR + cj * 16) = gvh[idx];
        }
    }
    __syncthreads();

    const int qq = lane >> 3, rr = lane & 7;
    const uint32_t qhB = smem_u32(sm + SQH);
    const uint32_t khB = smem_u32(sm + SKH);
    const uint32_t vhB = smem_u32(sm + SVH);
    const uint32_t aoff = (uint32_t)((wid * 16 + (qq & 1) * 8 + rr) * QSTR + (qq >> 1) * 16);
    const uint32_t krow = (uint32_t)((qq >> 1) * 8 + rr);     // B non-trans (K)
    const uint32_t kcol = (uint32_t)((qq & 1) * 16);
    const uint32_t vrow = (uint32_t)((qq & 1) * 8 + rr);      // B trans (V)
    const uint32_t vcol = (uint32_t)((qq >> 1) * 16);

    // Q fragments resident
    uint32_t qfr[4][4];
    #pragma unroll
    for (int ks = 0; ks < 4; ks++)
        ldm_x4(qfr[ks], qhB + aoff + ks * 32);

    float o[8][4];
    #pragma unroll
    for (int i = 0; i < 8; i++)
        #pragma unroll
        for (int j = 0; j < 4; j++) o[i][j] = 0.f;

    float m0 = -1e30f, m1 = -1e30f, l0 = 0.f, l1 = 0.f;
    const int gr = lane >> 2, gc = (lane & 3) * 2;
    const int row0 = q0 + wid * 16 + gr;
    const int diag_cb = (q0 + wid * 16) & ~63;   // warp-uniform

    auto do_chunk = [&](int cb, bool diag) {
        float s[8][4];
        #pragma unroll
        for (int i = 0; i < 8; i++)
            #pragma unroll
            for (int j = 0; j < 4; j++) s[i][j] = 0.f;

        // ---- S = Q @ K^T (1-pass, pre-scaled) ----
        #pragma unroll
        for (int ks = 0; ks < 4; ks++) {
            uint32_t kh[4][4];
            #pragma unroll
            for (int nt = 0; nt < 4; nt++) {
                uint32_t ro = (uint32_t)(cb + nt * 16 + krow) * QSTR + kcol + ks * 32;
                ldm_x4(kh[nt], khB + ro);
            }
            #pragma unroll
            for (int ni = 0; ni < 8; ni++)
                mma16816(s[ni], qfr[ks], &kh[ni >> 1][(ni & 1) * 2]);
        }

        // ---- causal mask (diagonal chunk only) ----
        if (diag) {
            #pragma unroll
            for (int ni = 0; ni < 8; ni++) {
                int col = cb + ni * 8 + gc;
                if (col     > row0)     s[ni][0] = -1e30f;
                if (col + 1 > row0)     s[ni][1] = -1e30f;
                if (col     > row0 + 8) s[ni][2] = -1e30f;
                if (col + 1 > row0 + 8) s[ni][3] = -1e30f;
            }
        }

        // ---- online softmax (base-2) ----
        float a0 = -1e30f, a1 = -1e30f;
        #pragma unroll
        for (int ni = 0; ni < 8; ni++) {
            a0 = fmaxf(a0, fmaxf(s[ni][0], s[ni][1]));
            a1 = fmaxf(a1, fmaxf(s[ni][2], s[ni][3]));
        }
        a0 = fmaxf(a0, __shfl_xor_sync(0xffffffffu, a0, 1));
        a0 = fmaxf(a0, __shfl_xor_sync(0xffffffffu, a0, 2));
        a1 = fmaxf(a1, __shfl_xor_sync(0xffffffffu, a1, 1));
        a1 = fmaxf(a1, __shfl_xor_sync(0xffffffffu, a1, 2));
        float mn0 = fmaxf(m0, a0), mn1 = fmaxf(m1, a1);
        float c0 = ex2f(m0 - mn0), c1 = ex2f(m1 - mn1);
        float ls0 = 0.f, ls1 = 0.f;
        #pragma unroll
        for (int ni = 0; ni < 8; ni++) {
            s[ni][0] = ex2f(s[ni][0] - mn0); ls0 += s[ni][0];
            s[ni][1] = ex2f(s[ni][1] - mn0); ls0 += s[ni][1];
            s[ni][2] = ex2f(s[ni][2] - mn1); ls1 += s[ni][2];
            s[ni][3] = ex2f(s[ni][3] - mn1); ls1 += s[ni][3];
        }
        l0 = l0 * c0 + ls0;
        l1 = l1 * c1 + ls1;
        m0 = mn0; m1 = mn1;
        #pragma unroll
        for (int ni = 0; ni < 8; ni++) {
            o[ni][0] *= c0; o[ni][1] *= c0;
            o[ni][2] *= c1; o[ni][3] *= c1;
        }

        // ---- O += P @ V (1-pass fp16 P; B-frags via ldmatrix.trans) ----
        #pragma unroll
        for (int g = 0; g < 4; g++) {
            uint32_t ph[4];
            ph[0] = pack2(__float2half_rn(s[2*g][0]),   __float2half_rn(s[2*g][1]));
            ph[1] = pack2(__float2half_rn(s[2*g][2]),   __float2half_rn(s[2*g][3]));
            ph[2] = pack2(__float2half_rn(s[2*g+1][0]), __float2half_rn(s[2*g+1][1]));
            ph[3] = pack2(__float2half_rn(s[2*g+1][2]), __float2half_rn(s[2*g+1][3]));
            #pragma unroll
            for (int nt = 0; nt < 4; nt++) {
                uint32_t ro = (uint32_t)(cb + g * 16 + vrow) * QSTR + nt * 32 + vcol;
                uint32_t vh[4];
                ldm_x4t(vh, vhB + ro);
                mma16816(o[nt * 2],     ph, &vh[0]);
                mma16816(o[nt * 2 + 1], ph, &vh[2]);
            }
        }
    };

    #pragma unroll 1
    for (int cb = 0; cb < diag_cb; cb += 64)
        do_chunk(cb, false);
    do_chunk(diag_cb, true);

    // ---- finalize (plain fp16 out) ----
    l0 += __shfl_xor_sync(0xffffffffu, l0, 1);
    l0 += __shfl_xor_sync(0xffffffffu, l0, 2);
    l1 += __shfl_xor_sync(0xffffffffu, l1, 1);
    l1 += __shfl_xor_sync(0xffffffffu, l1, 2);
    float i0 = 1.f / l0, i1 = 1.f / l1;

    size_t base0 = ((size_t)b * TT + row0) * CC + h * HS;
    size_t base1 = ((size_t)b * TT + row0 + 8) * CC + h * HS;
    #pragma unroll
    for (int ni = 0; ni < 8; ni++) {
        int d = ni * 8 + gc;
        *(uint32_t*)(g_oh + base0 + d) =
            pack2(__float2half_rn(o[ni][0] * i0), __float2half_rn(o[ni][1] * i0));
        *(uint32_t*)(g_oh + base1 + d) =
            pack2(__float2half_rn(o[ni][2] * i1), __float2half_rn(o[ni][3] * i1));
    }
}

// ---------------------------------------------------------------------------
extern "C" void kernel_launch(void* const* d_in, const int* in_sizes, int n_in,
                              void* d_out, int out_size)
{
    const float* x  = (const float*)d_in[0];
    const float* Wq = (const float*)d_in[1];
    const float* Wk = (const float*)d_in[2];
    const float* Wv = (const float*)d_in[3];
    const float* Wp = (const float*)d_in[4];
    const float* bp = (const float*)d_in[5];
    float* out = (float*)d_out;

    cudaFuncSetAttribute(gemm_kernel<0>,
                         cudaFuncAttributeMaxDynamicSharedMemorySize, GEMM_SMEM);
    cudaFuncSetAttribute(gemm_kernel<1>,
                         cudaFuncAttributeMaxDynamicSharedMemorySize, GEMM_SMEM);
    cudaFuncSetAttribute(attn_hmma_kernel,
                         cudaFuncAttributeMaxDynamicSharedMemorySize, ATTN_SMEM);

    cvt_kernel<<<CVT_XBLK + CVT_WBLK, 256>>>(x, Wq, Wk, Wv, Wp);
    gemm_kernel<0><<<dim3(MM / 128, 9), 256, GEMM_SMEM>>>(nullptr, nullptr);
    attn_hmma_kernel<<<dim3(2, BB * HH), 256, ATTN_SMEM>>>();
    gemm_kernel<1><<<dim3(MM / 128, CC / 128), 256, GEMM_SMEM>>>(bp, out);
}